// round 3
// baseline (speedup 1.0000x reference)
#include <cuda_runtime.h>

// Problem constants
#define NN 100000
#define CC 128
#define HH 8
#define DD 16
#define EE 640000

// -------- device scratch (static; no runtime allocation allowed) --------
__device__ float g_q[NN * CC];
__device__ float g_k[NN * CC];
__device__ float g_v[NN * CC];
__device__ float g_acc[NN * CC];
__device__ float g_s[EE * HH];       // stores exp(score)

#define SCORE_BLOCKS 512
#define SCORE_THREADS 256
#define TOTAL_WARPS (SCORE_BLOCKS * SCORE_THREADS / 32)   // 4096
__device__ float g_partial[TOTAL_WARPS * HH];
__device__ float g_inv_denom[HH];
__device__ int   g_is32;             // 1 if edge_index is int32, 0 if int64

// ======================================================================
// Detect edge_index dtype. If int64, every odd 32-bit word is the high
// half of a value < 2^31 -> 0. If int32, odd words are random node ids.
// ======================================================================
__global__ void detect_kernel(const int* __restrict__ ei_words)
{
    int any = 0;
    #pragma unroll
    for (int i = 0; i < 64; i++)
        any |= ei_words[2 * i + 1];
    g_is32 = (any != 0) ? 1 : 0;
}

// Fetch edge endpoints under either dtype, bounds-guarded.
__device__ __forceinline__ void load_edge(const void* ei, int is32, int e,
                                          int& row, int& col)
{
    if (is32) {
        row = ((const int*)ei)[e];
        col = ((const int*)ei)[EE + e];
    } else {
        row = (int)((const long long*)ei)[e];
        col = (int)((const long long*)ei)[EE + e];
    }
    if ((unsigned)row >= NN) row = 0;
    if ((unsigned)col >= NN) col = 0;
}

// ======================================================================
// Generic 128-K GEMM: out[N,128] = A[N,128] @ W^T[128,128] + bias
// Tile 128 rows x 128 cols, 256 threads, 8x8 register microtile.
// ======================================================================
#define WS_STRIDE 132
#define GEMM_SMEM ((128 * 128 + 128 * WS_STRIDE) * 4)

__global__ __launch_bounds__(256) void gemm128_kernel(
    const float* __restrict__ A,
    const float* __restrict__ W,
    const float* __restrict__ bias,
    float* __restrict__ out)
{
    extern __shared__ float smem[];
    float* a_s = smem;                 // 128*128
    float* w_s = smem + 128 * 128;     // 128*WS_STRIDE

    const int row0 = blockIdx.x * 128;
    const int tid  = threadIdx.x;
    const int tx   = tid & 15;         // col group
    const int ty   = tid >> 4;         // row group

    // ---- load A tile (coalesced) ----
    #pragma unroll
    for (int i = 0; i < 16; i++) {
        int f  = tid + i * 256;        // float4 index within tile
        int r  = f >> 5;               // 0..127
        int k4 = f & 31;               // 0..31
        float4 val = make_float4(0.f, 0.f, 0.f, 0.f);
        int gr = row0 + r;
        if (gr < NN) val = ((const float4*)A)[gr * 32 + k4];
        ((float4*)a_s)[r * 32 + k4] = val;
    }

    // ---- load W transposed: w_s[k][c] = W[c][k] ----
    #pragma unroll
    for (int i = 0; i < 16; i++) {
        int f  = tid + i * 256;
        int c  = f >> 5;
        int k4 = f & 31;
        float4 val = ((const float4*)W)[c * 32 + k4];
        w_s[(k4 * 4 + 0) * WS_STRIDE + c] = val.x;
        w_s[(k4 * 4 + 1) * WS_STRIDE + c] = val.y;
        w_s[(k4 * 4 + 2) * WS_STRIDE + c] = val.z;
        w_s[(k4 * 4 + 3) * WS_STRIDE + c] = val.w;
    }
    __syncthreads();

    float acc[8][8];
    #pragma unroll
    for (int i = 0; i < 8; i++)
        #pragma unroll
        for (int j = 0; j < 8; j++) acc[i][j] = 0.f;

    #pragma unroll 2
    for (int k = 0; k < 128; k++) {
        float a[8], b[8];
        #pragma unroll
        for (int i = 0; i < 8; i++) a[i] = a_s[(ty * 8 + i) * 128 + k];
        float4 b0 = *(const float4*)&w_s[k * WS_STRIDE + tx * 8];
        float4 b1 = *(const float4*)&w_s[k * WS_STRIDE + tx * 8 + 4];
        b[0] = b0.x; b[1] = b0.y; b[2] = b0.z; b[3] = b0.w;
        b[4] = b1.x; b[5] = b1.y; b[6] = b1.z; b[7] = b1.w;
        #pragma unroll
        for (int i = 0; i < 8; i++)
            #pragma unroll
            for (int j = 0; j < 8; j++)
                acc[i][j] = fmaf(a[i], b[j], acc[i][j]);
    }

    // ---- bias + store (vectorized) ----
    float4 bv0 = *(const float4*)&bias[tx * 8];
    float4 bv1 = *(const float4*)&bias[tx * 8 + 4];
    #pragma unroll
    for (int i = 0; i < 8; i++) {
        int gr = row0 + ty * 8 + i;
        if (gr < NN) {
            float4 o0 = make_float4(acc[i][0] + bv0.x, acc[i][1] + bv0.y,
                                    acc[i][2] + bv0.z, acc[i][3] + bv0.w);
            float4 o1 = make_float4(acc[i][4] + bv1.x, acc[i][5] + bv1.y,
                                    acc[i][6] + bv1.z, acc[i][7] + bv1.w);
            ((float4*)out)[gr * 32 + tx * 2 + 0] = o0;
            ((float4*)out)[gr * 32 + tx * 2 + 1] = o1;
        }
    }
}

// ======================================================================
// Zero the accumulator
// ======================================================================
__global__ void zero_kernel()
{
    const int n4 = NN * CC / 4;
    for (int i = blockIdx.x * blockDim.x + threadIdx.x; i < n4;
         i += gridDim.x * blockDim.x)
        ((float4*)g_acc)[i] = make_float4(0.f, 0.f, 0.f, 0.f);
}

// ======================================================================
// Scores: one warp per edge (grid-stride). lane l covers floats [4l,4l+4),
// head h = l>>2. Writes exp(score) and deterministic per-warp head sums.
// ======================================================================
__global__ __launch_bounds__(SCORE_THREADS) void score_kernel(
    const void* __restrict__ ei)
{
    const int lane = threadIdx.x & 31;
    const int warp = (blockIdx.x * blockDim.x + threadIdx.x) >> 5;
    const int h = lane >> 2;
    const int is32 = g_is32;
    float hsum = 0.f;

    for (int e = warp; e < EE; e += TOTAL_WARPS) {
        int row, col;
        load_edge(ei, is32, e, row, col);
        float4 q4 = ((const float4*)g_q)[row * 32 + lane];
        float4 k4 = ((const float4*)g_k)[col * 32 + lane];
        float p = q4.x * k4.x + q4.y * k4.y + q4.z * k4.z + q4.w * k4.w;
        p += __shfl_xor_sync(0xFFFFFFFFu, p, 1);
        p += __shfl_xor_sync(0xFFFFFFFFu, p, 2);
        float w = __expf(p * 0.25f);   // scale = 1/sqrt(16)
        if ((lane & 3) == 0) {
            g_s[e * 8 + h] = w;
            hsum += w;                 // fixed iteration order -> deterministic
        }
    }
    if ((lane & 3) == 0) g_partial[warp * 8 + h] = hsum;
}

// ======================================================================
// Deterministic denominator reduction: 1 block, fixed summation order.
// ======================================================================
__global__ void denom_kernel()
{
    __shared__ float sh[256];
    const int t = threadIdx.x;
    const int h = t & 7;
    const int i0 = t >> 3;  // 0..31
    float s = 0.f;
    for (int i = i0; i < TOTAL_WARPS; i += 32)
        s += g_partial[i * 8 + h];
    sh[t] = s;
    __syncthreads();
    if (t < 8) {
        float tot = 0.f;
        #pragma unroll
        for (int j = 0; j < 32; j++) tot += sh[t + j * 8];
        g_inv_denom[t] = 1.0f / tot;
    }
}

// ======================================================================
// Scatter: one warp per edge, atomicAdd into g_acc[row].
// ======================================================================
__global__ __launch_bounds__(256) void scatter_kernel(
    const void* __restrict__ ei)
{
    const int lane = threadIdx.x & 31;
    const int warp = (blockIdx.x * blockDim.x + threadIdx.x) >> 5;
    const int nwarps = (gridDim.x * blockDim.x) >> 5;
    const int h = lane >> 2;
    const int is32 = g_is32;
    const float inv = g_inv_denom[h];

    for (int e = warp; e < EE; e += nwarps) {
        int row, col;
        load_edge(ei, is32, e, row, col);
        float w = g_s[e * 8 + h] * inv;
        float4 v4 = ((const float4*)g_v)[col * 32 + lane];
        float* dst = &g_acc[row * 128 + lane * 4];
        atomicAdd(dst + 0, w * v4.x);
        atomicAdd(dst + 1, w * v4.y);
        atomicAdd(dst + 2, w * v4.z);
        atomicAdd(dst + 3, w * v4.w);
    }
}

// ======================================================================
// kernel_launch
// inputs (metadata order): features, edge_index, Wq, bq, Wk, bk,
//                          Wv, bv, Wo, bo
// ======================================================================
extern "C" void kernel_launch(void* const* d_in, const int* in_sizes, int n_in,
                              void* d_out, int out_size)
{
    const float* feat = (const float*)d_in[0];
    const void*  ei   = d_in[1];
    const float* Wq   = (const float*)d_in[2];
    const float* bq   = (const float*)d_in[3];
    const float* Wk   = (const float*)d_in[4];
    const float* bk   = (const float*)d_in[5];
    const float* Wv   = (const float*)d_in[6];
    const float* bv   = (const float*)d_in[7];
    const float* Wo   = (const float*)d_in[8];
    const float* bo   = (const float*)d_in[9];
    float* out = (float*)d_out;

    cudaFuncSetAttribute(gemm128_kernel,
                         cudaFuncAttributeMaxDynamicSharedMemorySize, GEMM_SMEM);

    float* q;   cudaGetSymbolAddress((void**)&q,   g_q);
    float* k;   cudaGetSymbolAddress((void**)&k,   g_k);
    float* v;   cudaGetSymbolAddress((void**)&v,   g_v);
    float* acc; cudaGetSymbolAddress((void**)&acc, g_acc);

    const int gemm_blocks = (NN + 127) / 128;  // 782

    detect_kernel<<<1, 1>>>((const int*)ei);
    zero_kernel<<<512, 256>>>();

    gemm128_kernel<<<gemm_blocks, 256, GEMM_SMEM>>>(feat, Wq, bq, q);
    gemm128_kernel<<<gemm_blocks, 256, GEMM_SMEM>>>(feat, Wk, bk, k);
    gemm128_kernel<<<gemm_blocks, 256, GEMM_SMEM>>>(feat, Wv, bv, v);

    score_kernel<<<SCORE_BLOCKS, SCORE_THREADS>>>(ei);
    denom_kernel<<<1, 256>>>();
    scatter_kernel<<<1184, 256>>>(ei);

    gemm128_kernel<<<gemm_blocks, 256, GEMM_SMEM>>>(acc, Wo, bo, out);
}

// round 5
// speedup vs baseline: 1.5173x; 1.5173x over previous
#include <cuda_runtime.h>
#include <cuda_bf16.h>
#include <cstdint>

// Problem constants
#define NN 100000
#define CC 128
#define HH 8
#define DD 16
#define EE 640000

// -------- device scratch (static; no runtime allocation allowed) --------
__device__ float g_q[NN * CC];
__device__ float g_k[NN * CC];
__device__ float g_v[NN * CC];
__device__ float g_acc[NN * CC];
__device__ float g_s[EE * HH];       // stores exp(score)

#define SCORE_BLOCKS 512
#define SCORE_THREADS 256
#define TOTAL_WARPS (SCORE_BLOCKS * SCORE_THREADS / 32)   // 4096
__device__ float g_partial[TOTAL_WARPS * HH];
__device__ float g_inv_denom[HH];
__device__ int   g_is32;             // 1 if edge_index is int32, 0 if int64

// ======================================================================
// Detect edge_index dtype (int32 vs int64)
// ======================================================================
__global__ void detect_kernel(const int* __restrict__ ei_words)
{
    int any = 0;
    #pragma unroll
    for (int i = 0; i < 64; i++)
        any |= ei_words[2 * i + 1];
    g_is32 = (any != 0) ? 1 : 0;
}

__device__ __forceinline__ void load_edge(const void* ei, int is32, int e,
                                          int& row, int& col)
{
    if (is32) {
        row = ((const int*)ei)[e];
        col = ((const int*)ei)[EE + e];
    } else {
        row = (int)((const long long*)ei)[e];
        col = (int)((const long long*)ei)[EE + e];
    }
    if ((unsigned)row >= NN) row = 0;
    if ((unsigned)col >= NN) col = 0;
}

// ======================================================================
// mma.sync helpers
// ======================================================================
__device__ __forceinline__ uint32_t smem_u32(const void* p) {
    uint32_t a;
    asm("{ .reg .u64 t; cvta.to.shared.u64 t, %1; cvt.u32.u64 %0, t; }"
        : "=r"(a) : "l"(p));
    return a;
}

__device__ __forceinline__ void ldsm_x4(uint32_t addr, uint32_t& r0, uint32_t& r1,
                                        uint32_t& r2, uint32_t& r3) {
    asm volatile("ldmatrix.sync.aligned.m8n8.x4.shared.b16 {%0,%1,%2,%3}, [%4];"
                 : "=r"(r0), "=r"(r1), "=r"(r2), "=r"(r3) : "r"(addr));
}
__device__ __forceinline__ void ldsm_x2(uint32_t addr, uint32_t& r0, uint32_t& r1) {
    asm volatile("ldmatrix.sync.aligned.m8n8.x2.shared.b16 {%0,%1}, [%2];"
                 : "=r"(r0), "=r"(r1) : "r"(addr));
}
__device__ __forceinline__ void mma16816(float* c, const uint32_t* a,
                                         const uint32_t* b) {
    asm volatile(
        "mma.sync.aligned.m16n8k16.row.col.f32.bf16.bf16.f32 "
        "{%0,%1,%2,%3}, {%4,%5,%6,%7}, {%8,%9}, {%0,%1,%2,%3};"
        : "+f"(c[0]), "+f"(c[1]), "+f"(c[2]), "+f"(c[3])
        : "r"(a[0]), "r"(a[1]), "r"(a[2]), "r"(a[3]), "r"(b[0]), "r"(b[1]));
}

// ======================================================================
// Tensor-core GEMM via mma.sync bf16 2-way split:
//   out[N,128] = A[N,128] @ W^T[128,128] + bias
// a*b ~= aH*bH + aH*bL + aL*bH   (fp32 accumulate; err ~2^-16)
// Tile: 128 rows x 128 cols, 256 threads (8 warps, 4x2).
// ======================================================================
#define TSTRIDE 136                          // bf16 elems per smem row (16B-aligned)
#define TILE_BF16 (128 * TSTRIDE)            // elems per tile
#define SM_TOTAL (4 * TILE_BF16 * 2)         // bytes: aH,aL,wH,wL

__global__ __launch_bounds__(256) void gemm_mma_kernel(
    const float* __restrict__ A,
    const float* __restrict__ W,
    const float* __restrict__ bias,
    float* __restrict__ out)
{
    extern __shared__ __nv_bfloat16 smem[];
    __nv_bfloat16* a_hi = smem;
    __nv_bfloat16* a_lo = smem + TILE_BF16;
    __nv_bfloat16* w_hi = smem + 2 * TILE_BF16;
    __nv_bfloat16* w_lo = smem + 3 * TILE_BF16;

    const int tid  = threadIdx.x;
    const int wid  = tid >> 5;
    const int lane = tid & 31;
    const int row0 = blockIdx.x * 128;

    // ---- load + split-convert A and W tiles ----
    #pragma unroll
    for (int i = 0; i < 16; i++) {
        int f  = tid + i * 256;       // float4 index 0..4095
        int r  = f >> 5;              // 0..127
        int c4 = f & 31;              // 0..31
        // A (guarded)
        float4 va = make_float4(0.f, 0.f, 0.f, 0.f);
        int gr = row0 + r;
        if (gr < NN) va = ((const float4*)A)[gr * 32 + c4];
        // W (always in-range)
        float4 vw = ((const float4*)W)[r * 32 + c4];

        int off = r * TSTRIDE + c4 * 4;
        #pragma unroll
        for (int j = 0; j < 4; j++) {
            float av = (j == 0) ? va.x : (j == 1) ? va.y : (j == 2) ? va.z : va.w;
            float wv = (j == 0) ? vw.x : (j == 1) ? vw.y : (j == 2) ? vw.z : vw.w;
            __nv_bfloat16 ah = __float2bfloat16(av);
            __nv_bfloat16 wh = __float2bfloat16(wv);
            a_hi[off + j] = ah;
            a_lo[off + j] = __float2bfloat16(av - __bfloat162float(ah));
            w_hi[off + j] = wh;
            w_lo[off + j] = __float2bfloat16(wv - __bfloat162float(wh));
        }
    }
    __syncthreads();

    // ---- warp tiling: 4 (m) x 2 (n); each warp 32 rows x 64 cols ----
    const int m_warp = (wid >> 1) * 32;
    const int n_warp = (wid & 1) * 64;

    // ldmatrix lane addresses (bytes)
    // A x4: rows m0 + (lane&15), k-half 8*(lane>>4)
    const uint32_t aH_base = smem_u32(a_hi);
    const uint32_t aL_base = smem_u32(a_lo);
    const uint32_t wH_base = smem_u32(w_hi);
    const uint32_t wL_base = smem_u32(w_lo);
    const uint32_t a_lane_off =
        (uint32_t)(((lane & 15)) * TSTRIDE + 8 * (lane >> 4)) * 2;
    const uint32_t b_lane_off =
        (uint32_t)(((lane & 7)) * TSTRIDE + 8 * ((lane >> 3) & 1)) * 2;

    float acc[2][8][4];
    #pragma unroll
    for (int mt = 0; mt < 2; mt++)
        #pragma unroll
        for (int nt = 0; nt < 8; nt++)
            #pragma unroll
            for (int j = 0; j < 4; j++) acc[mt][nt][j] = 0.f;

    #pragma unroll
    for (int kt = 0; kt < 8; kt++) {
        const uint32_t koff = kt * 32;   // 16 bf16 = 32 bytes
        uint32_t aH[2][4], aL[2][4];
        #pragma unroll
        for (int mt = 0; mt < 2; mt++) {
            uint32_t ra = (uint32_t)((m_warp + mt * 16) * TSTRIDE * 2) + a_lane_off + koff;
            ldsm_x4(aH_base + ra, aH[mt][0], aH[mt][1], aH[mt][2], aH[mt][3]);
            ldsm_x4(aL_base + ra, aL[mt][0], aL[mt][1], aL[mt][2], aL[mt][3]);
        }
        #pragma unroll
        for (int nt = 0; nt < 8; nt++) {
            uint32_t rb = (uint32_t)((n_warp + nt * 8) * TSTRIDE * 2) + b_lane_off + koff;
            uint32_t bH[2], bL[2];
            ldsm_x2(wH_base + rb, bH[0], bH[1]);
            ldsm_x2(wL_base + rb, bL[0], bL[1]);
            #pragma unroll
            for (int mt = 0; mt < 2; mt++) {
                mma16816(acc[mt][nt], aH[mt], bH);
                mma16816(acc[mt][nt], aH[mt], bL);
                mma16816(acc[mt][nt], aL[mt], bH);
            }
        }
    }

    // ---- epilogue: regs -> +bias -> gmem ----
    const int qrow = lane >> 2;           // 0..7
    const int qcol = (lane & 3) * 2;      // 0,2,4,6
    #pragma unroll
    for (int mt = 0; mt < 2; mt++) {
        #pragma unroll
        for (int half = 0; half < 2; half++) {   // c0/c1 vs c2/c3 (row, row+8)
            int grow = row0 + m_warp + mt * 16 + qrow + half * 8;
            if (grow < NN) {
                #pragma unroll
                for (int nt = 0; nt < 8; nt++) {
                    int col = n_warp + nt * 8 + qcol;
                    float2 o;
                    o.x = acc[mt][nt][half * 2 + 0] + __ldg(&bias[col]);
                    o.y = acc[mt][nt][half * 2 + 1] + __ldg(&bias[col + 1]);
                    *(float2*)&out[grow * 128 + col] = o;
                }
            }
        }
    }
}

// ======================================================================
// Zero the accumulator
// ======================================================================
__global__ void zero_kernel()
{
    const int n4 = NN * CC / 4;
    for (int i = blockIdx.x * blockDim.x + threadIdx.x; i < n4;
         i += gridDim.x * blockDim.x)
        ((float4*)g_acc)[i] = make_float4(0.f, 0.f, 0.f, 0.f);
}

// ======================================================================
// Scores: one warp per edge (grid-stride), deterministic partial sums.
// ======================================================================
__global__ __launch_bounds__(SCORE_THREADS) void score_kernel(
    const void* __restrict__ ei)
{
    const int lane = threadIdx.x & 31;
    const int warp = (blockIdx.x * blockDim.x + threadIdx.x) >> 5;
    const int h = lane >> 2;
    const int is32 = g_is32;
    float hsum = 0.f;

    for (int e = warp; e < EE; e += TOTAL_WARPS) {
        int row, col;
        load_edge(ei, is32, e, row, col);
        float4 q4 = ((const float4*)g_q)[row * 32 + lane];
        float4 k4 = ((const float4*)g_k)[col * 32 + lane];
        float p = q4.x * k4.x + q4.y * k4.y + q4.z * k4.z + q4.w * k4.w;
        p += __shfl_xor_sync(0xFFFFFFFFu, p, 1);
        p += __shfl_xor_sync(0xFFFFFFFFu, p, 2);
        float w = __expf(p * 0.25f);   // scale = 1/sqrt(16)
        if ((lane & 3) == 0) {
            g_s[e * 8 + h] = w;
            hsum += w;
        }
    }
    if ((lane & 3) == 0) g_partial[warp * 8 + h] = hsum;
}

// ======================================================================
// Deterministic denominator reduction: 1 block, fixed summation order.
// ======================================================================
__global__ void denom_kernel()
{
    __shared__ float sh[256];
    const int t = threadIdx.x;
    const int h = t & 7;
    const int i0 = t >> 3;  // 0..31
    float s = 0.f;
    for (int i = i0; i < TOTAL_WARPS; i += 32)
        s += g_partial[i * 8 + h];
    sh[t] = s;
    __syncthreads();
    if (t < 8) {
        float tot = 0.f;
        #pragma unroll
        for (int j = 0; j < 32; j++) tot += sh[t + j * 8];
        g_inv_denom[t] = 1.0f / tot;
    }
}

// ======================================================================
// Scatter: one warp per edge, atomicAdd into g_acc[row].
// ======================================================================
__global__ __launch_bounds__(256) void scatter_kernel(
    const void* __restrict__ ei)
{
    const int lane = threadIdx.x & 31;
    const int warp = (blockIdx.x * blockDim.x + threadIdx.x) >> 5;
    const int nwarps = (gridDim.x * blockDim.x) >> 5;
    const int h = lane >> 2;
    const int is32 = g_is32;
    const float inv = g_inv_denom[h];

    for (int e = warp; e < EE; e += nwarps) {
        int row, col;
        load_edge(ei, is32, e, row, col);
        float w = g_s[e * 8 + h] * inv;
        float4 v4 = ((const float4*)g_v)[col * 32 + lane];
        float* dst = &g_acc[row * 128 + lane * 4];
        atomicAdd(dst + 0, w * v4.x);
        atomicAdd(dst + 1, w * v4.y);
        atomicAdd(dst + 2, w * v4.z);
        atomicAdd(dst + 3, w * v4.w);
    }
}

// ======================================================================
// kernel_launch
// ======================================================================
extern "C" void kernel_launch(void* const* d_in, const int* in_sizes, int n_in,
                              void* d_out, int out_size)
{
    const float* feat = (const float*)d_in[0];
    const void*  ei   = d_in[1];
    const float* Wq   = (const float*)d_in[2];
    const float* bq   = (const float*)d_in[3];
    const float* Wk   = (const float*)d_in[4];
    const float* bk   = (const float*)d_in[5];
    const float* Wv   = (const float*)d_in[6];
    const float* bv   = (const float*)d_in[7];
    const float* Wo   = (const float*)d_in[8];
    const float* bo   = (const float*)d_in[9];
    float* out = (float*)d_out;

    cudaFuncSetAttribute(gemm_mma_kernel,
                         cudaFuncAttributeMaxDynamicSharedMemorySize, SM_TOTAL);

    float* q;   cudaGetSymbolAddress((void**)&q,   g_q);
    float* k;   cudaGetSymbolAddress((void**)&k,   g_k);
    float* v;   cudaGetSymbolAddress((void**)&v,   g_v);
    float* acc; cudaGetSymbolAddress((void**)&acc, g_acc);

    const int gemm_blocks = (NN + 127) / 128;  // 782

    detect_kernel<<<1, 1>>>((const int*)ei);
    zero_kernel<<<512, 256>>>();

    gemm_mma_kernel<<<gemm_blocks, 256, SM_TOTAL>>>(feat, Wq, bq, q);
    gemm_mma_kernel<<<gemm_blocks, 256, SM_TOTAL>>>(feat, Wk, bk, k);
    gemm_mma_kernel<<<gemm_blocks, 256, SM_TOTAL>>>(feat, Wv, bv, v);

    score_kernel<<<SCORE_BLOCKS, SCORE_THREADS>>>(ei);
    denom_kernel<<<1, 256>>>();
    scatter_kernel<<<1184, 256>>>(ei);

    gemm_mma_kernel<<<gemm_blocks, 256, SM_TOTAL>>>(acc, Wo, bo, out);
}

// round 7
// speedup vs baseline: 1.8249x; 1.2027x over previous
#include <cuda_runtime.h>
#include <cuda_bf16.h>
#include <cstdint>

// Problem constants
#define NN 100000
#define CC 128
#define HH 8
#define DD 16
#define EE 640000

// -------- device scratch (static; no runtime allocation allowed) --------
__device__ float g_q[NN * CC];
__device__ float g_k[NN * CC];
__device__ float g_v[NN * CC];
__device__ float g_acc[NN * CC];
__device__ int   g_hist[NN];
__device__ int   g_cursor[NN];
__device__ int   g_rowptr[NN + 1];
__device__ int   g_ecol[EE];

#define GATHER_BLOCKS 512
#define GATHER_THREADS 256
#define TOTAL_WARPS (GATHER_BLOCKS * GATHER_THREADS / 32)   // 4096
__device__ float g_partial[TOTAL_WARPS * HH];
__device__ float g_inv_denom[HH];
__device__ int   g_is32;             // 1 if edge_index is int32, 0 if int64

// ======================================================================
// Detect edge_index dtype (int32 vs int64)
// ======================================================================
__global__ void detect_kernel(const int* __restrict__ ei_words)
{
    int any = 0;
    #pragma unroll
    for (int i = 0; i < 64; i++)
        any |= ei_words[2 * i + 1];
    g_is32 = (any != 0) ? 1 : 0;
}

__device__ __forceinline__ void load_edge(const void* ei, int is32, int e,
                                          int& row, int& col)
{
    if (is32) {
        row = ((const int*)ei)[e];
        col = ((const int*)ei)[EE + e];
    } else {
        row = (int)((const long long*)ei)[e];
        col = (int)((const long long*)ei)[EE + e];
    }
    if ((unsigned)row >= NN) row = 0;
    if ((unsigned)col >= NN) col = 0;
}

// ======================================================================
// CSR build: zero -> count -> scan -> fill
// ======================================================================
__global__ void zero_hist_kernel()
{
    for (int i = blockIdx.x * blockDim.x + threadIdx.x; i < NN;
         i += gridDim.x * blockDim.x) {
        g_hist[i] = 0;
        g_cursor[i] = 0;
    }
}

__global__ void count_kernel(const void* __restrict__ ei)
{
    const int is32 = g_is32;
    for (int e = blockIdx.x * blockDim.x + threadIdx.x; e < EE;
         e += gridDim.x * blockDim.x) {
        int row, col;
        load_edge(ei, is32, e, row, col);
        atomicAdd(&g_hist[row], 1);
    }
}

__global__ __launch_bounds__(1024) void scan_kernel()
{
    __shared__ int sh[1024];
    const int t = threadIdx.x;
    const int CH = (NN + 1023) / 1024;   // 98
    const int start = t * CH;
    const int end = min(start + CH, NN);
    int s = 0;
    for (int i = start; i < end; i++) s += g_hist[i];
    sh[t] = s;
    __syncthreads();
    for (int off = 1; off < 1024; off <<= 1) {
        int v = (t >= off) ? sh[t - off] : 0;
        __syncthreads();
        sh[t] += v;
        __syncthreads();
    }
    int base = (t == 0) ? 0 : sh[t - 1];
    for (int i = start; i < end; i++) {
        int c = g_hist[i];
        g_rowptr[i] = base;
        base += c;
    }
    if (t == 1023) g_rowptr[NN] = sh[1023];
}

__global__ void fill_kernel(const void* __restrict__ ei)
{
    const int is32 = g_is32;
    for (int e = blockIdx.x * blockDim.x + threadIdx.x; e < EE;
         e += gridDim.x * blockDim.x) {
        int row, col;
        load_edge(ei, is32, e, row, col);
        int slot = atomicAdd(&g_cursor[row], 1);
        g_ecol[g_rowptr[row] + slot] = col;
    }
}

// ======================================================================
// mma.sync helpers
// ======================================================================
__device__ __forceinline__ uint32_t smem_u32(const void* p) {
    uint32_t a;
    asm("{ .reg .u64 t; cvta.to.shared.u64 t, %1; cvt.u32.u64 %0, t; }"
        : "=r"(a) : "l"(p));
    return a;
}
__device__ __forceinline__ void ldsm_x4(uint32_t addr, uint32_t& r0, uint32_t& r1,
                                        uint32_t& r2, uint32_t& r3) {
    asm volatile("ldmatrix.sync.aligned.m8n8.x4.shared.b16 {%0,%1,%2,%3}, [%4];"
                 : "=r"(r0), "=r"(r1), "=r"(r2), "=r"(r3) : "r"(addr));
}
__device__ __forceinline__ void ldsm_x2(uint32_t addr, uint32_t& r0, uint32_t& r1) {
    asm volatile("ldmatrix.sync.aligned.m8n8.x2.shared.b16 {%0,%1}, [%2];"
                 : "=r"(r0), "=r"(r1) : "r"(addr));
}
__device__ __forceinline__ void mma16816(float* c, const uint32_t* a,
                                         const uint32_t* b) {
    asm volatile(
        "mma.sync.aligned.m16n8k16.row.col.f32.bf16.bf16.f32 "
        "{%0,%1,%2,%3}, {%4,%5,%6,%7}, {%8,%9}, {%0,%1,%2,%3};"
        : "+f"(c[0]), "+f"(c[1]), "+f"(c[2]), "+f"(c[3])
        : "r"(a[0]), "r"(a[1]), "r"(a[2]), "r"(a[3]), "r"(b[0]), "r"(b[1]));
}

// ======================================================================
// GEMM building blocks (bf16 2-way split, fp32 accumulate)
// Tile: 128 rows x 128 cols, 256 threads (8 warps, 4x2).
// ======================================================================
#define TSTRIDE 136
#define TILE_BF16 (128 * TSTRIDE)
#define SM_TOTAL (4 * TILE_BF16 * 2)

__device__ __forceinline__ void split_store(__nv_bfloat16* hi, __nv_bfloat16* lo,
                                            int off, float4 v) {
    #pragma unroll
    for (int j = 0; j < 4; j++) {
        float x = (j == 0) ? v.x : (j == 1) ? v.y : (j == 2) ? v.z : v.w;
        __nv_bfloat16 h = __float2bfloat16(x);
        hi[off + j] = h;
        lo[off + j] = __float2bfloat16(x - __bfloat162float(h));
    }
}

// Convert W[128x128] into wH/wL smem tiles
__device__ __forceinline__ void conv_w(const float* __restrict__ W,
                                       __nv_bfloat16* w_hi, __nv_bfloat16* w_lo,
                                       int tid) {
    #pragma unroll
    for (int i = 0; i < 16; i++) {
        int f  = tid + i * 256;
        int r  = f >> 5;
        int c4 = f & 31;
        float4 vw = ((const float4*)W)[r * 32 + c4];
        split_store(w_hi, w_lo, r * TSTRIDE + c4 * 4, vw);
    }
}

// MMA compute + epilogue for one weight (A already in aH/aL smem)
__device__ __forceinline__ void mma_compute_store(
    const __nv_bfloat16* a_hi, const __nv_bfloat16* a_lo,
    const __nv_bfloat16* w_hi, const __nv_bfloat16* w_lo,
    const float* __restrict__ bias, float* __restrict__ out,
    int row0, int wid, int lane)
{
    const int m_warp = (wid >> 1) * 32;
    const int n_warp = (wid & 1) * 64;
    const uint32_t aH_base = smem_u32(a_hi);
    const uint32_t aL_base = smem_u32(a_lo);
    const uint32_t wH_base = smem_u32(w_hi);
    const uint32_t wL_base = smem_u32(w_lo);
    const uint32_t a_lane_off =
        (uint32_t)(((lane & 15)) * TSTRIDE + 8 * (lane >> 4)) * 2;
    const uint32_t b_lane_off =
        (uint32_t)(((lane & 7)) * TSTRIDE + 8 * ((lane >> 3) & 1)) * 2;

    float acc[2][8][4];
    #pragma unroll
    for (int mt = 0; mt < 2; mt++)
        #pragma unroll
        for (int nt = 0; nt < 8; nt++)
            #pragma unroll
            for (int j = 0; j < 4; j++) acc[mt][nt][j] = 0.f;

    #pragma unroll
    for (int kt = 0; kt < 8; kt++) {
        const uint32_t koff = kt * 32;
        uint32_t aH[2][4], aL[2][4];
        #pragma unroll
        for (int mt = 0; mt < 2; mt++) {
            uint32_t ra = (uint32_t)((m_warp + mt * 16) * TSTRIDE * 2) + a_lane_off + koff;
            ldsm_x4(aH_base + ra, aH[mt][0], aH[mt][1], aH[mt][2], aH[mt][3]);
            ldsm_x4(aL_base + ra, aL[mt][0], aL[mt][1], aL[mt][2], aL[mt][3]);
        }
        #pragma unroll
        for (int nt = 0; nt < 8; nt++) {
            uint32_t rb = (uint32_t)((n_warp + nt * 8) * TSTRIDE * 2) + b_lane_off + koff;
            uint32_t bH[2], bL[2];
            ldsm_x2(wH_base + rb, bH[0], bH[1]);
            ldsm_x2(wL_base + rb, bL[0], bL[1]);
            #pragma unroll
            for (int mt = 0; mt < 2; mt++) {
                mma16816(acc[mt][nt], aH[mt], bH);
                mma16816(acc[mt][nt], aH[mt], bL);
                mma16816(acc[mt][nt], aL[mt], bH);
            }
        }
    }

    const int qrow = lane >> 2;
    const int qcol = (lane & 3) * 2;
    #pragma unroll
    for (int mt = 0; mt < 2; mt++) {
        #pragma unroll
        for (int half = 0; half < 2; half++) {
            int grow = row0 + m_warp + mt * 16 + qrow + half * 8;
            if (grow < NN) {
                #pragma unroll
                for (int nt = 0; nt < 8; nt++) {
                    int col = n_warp + nt * 8 + qcol;
                    float2 o;
                    o.x = acc[mt][nt][half * 2 + 0] + __ldg(&bias[col]);
                    o.y = acc[mt][nt][half * 2 + 1] + __ldg(&bias[col + 1]);
                    *(float2*)&out[grow * 128 + col] = o;
                }
            }
        }
    }
}

// Fused Q/K/V GEMM: load+convert feat tile once, 3 weights
__global__ __launch_bounds__(256) void gemm_qkv_kernel(
    const float* __restrict__ A,
    const float* __restrict__ Wq, const float* __restrict__ bq, float* __restrict__ oq,
    const float* __restrict__ Wk, const float* __restrict__ bk, float* __restrict__ ok,
    const float* __restrict__ Wv, const float* __restrict__ bv, float* __restrict__ ov)
{
    extern __shared__ __nv_bfloat16 smem[];
    __nv_bfloat16* a_hi = smem;
    __nv_bfloat16* a_lo = smem + TILE_BF16;
    __nv_bfloat16* w_hi = smem + 2 * TILE_BF16;
    __nv_bfloat16* w_lo = smem + 3 * TILE_BF16;

    const int tid  = threadIdx.x;
    const int wid  = tid >> 5;
    const int lane = tid & 31;
    const int row0 = blockIdx.x * 128;

    #pragma unroll
    for (int i = 0; i < 16; i++) {
        int f  = tid + i * 256;
        int r  = f >> 5;
        int c4 = f & 31;
        float4 va = make_float4(0.f, 0.f, 0.f, 0.f);
        int gr = row0 + r;
        if (gr < NN) va = ((const float4*)A)[gr * 32 + c4];
        split_store(a_hi, a_lo, r * TSTRIDE + c4 * 4, va);
    }

    const float* Ws[3] = {Wq, Wk, Wv};
    const float* bs[3] = {bq, bk, bv};
    float*       os[3] = {oq, ok, ov};
    #pragma unroll 1
    for (int w = 0; w < 3; w++) {
        conv_w(Ws[w], w_hi, w_lo, tid);
        __syncthreads();
        mma_compute_store(a_hi, a_lo, w_hi, w_lo, bs[w], os[w], row0, wid, lane);
        __syncthreads();
    }
}

// Single GEMM with optional per-head column scale on A (for final Wo GEMM)
__global__ __launch_bounds__(256) void gemm_mma_kernel(
    const float* __restrict__ A,
    const float* __restrict__ W,
    const float* __restrict__ bias,
    float* __restrict__ out,
    const float* __restrict__ colscale)
{
    extern __shared__ __nv_bfloat16 smem[];
    __nv_bfloat16* a_hi = smem;
    __nv_bfloat16* a_lo = smem + TILE_BF16;
    __nv_bfloat16* w_hi = smem + 2 * TILE_BF16;
    __nv_bfloat16* w_lo = smem + 3 * TILE_BF16;

    const int tid  = threadIdx.x;
    const int wid  = tid >> 5;
    const int lane = tid & 31;
    const int row0 = blockIdx.x * 128;

    #pragma unroll
    for (int i = 0; i < 16; i++) {
        int f  = tid + i * 256;
        int r  = f >> 5;
        int c4 = f & 31;
        float4 va = make_float4(0.f, 0.f, 0.f, 0.f);
        int gr = row0 + r;
        if (gr < NN) va = ((const float4*)A)[gr * 32 + c4];
        if (colscale) {
            float sc = __ldg(&colscale[c4 >> 2]);   // head = (c4*4)/16
            va.x *= sc; va.y *= sc; va.z *= sc; va.w *= sc;
        }
        split_store(a_hi, a_lo, r * TSTRIDE + c4 * 4, va);
    }
    conv_w(W, w_hi, w_lo, tid);
    __syncthreads();
    mma_compute_store(a_hi, a_lo, w_hi, w_lo, bias, out, row0, wid, lane);
}

// ======================================================================
// Gather: one warp per node. Unnormalized accumulate + denom partials.
// lane l: floats [4l, 4l+4) of the 128-channel row; head h = l>>2.
// ======================================================================
__global__ __launch_bounds__(GATHER_THREADS) void gather_kernel()
{
    const int lane = threadIdx.x & 31;
    const int warp = (blockIdx.x * blockDim.x + threadIdx.x) >> 5;
    const int h = lane >> 2;
    float hsum = 0.f;

    for (int n = warp; n < NN; n += TOTAL_WARPS) {
        float4 q4 = ((const float4*)g_q)[n * 32 + lane];
        float4 a = make_float4(0.f, 0.f, 0.f, 0.f);
        const int beg = g_rowptr[n];
        const int end = g_rowptr[n + 1];
        for (int j = beg; j < end; j++) {
            int col = g_ecol[j];
            float4 k4 = ((const float4*)g_k)[col * 32 + lane];
            float4 v4 = ((const float4*)g_v)[col * 32 + lane];
            float p = q4.x * k4.x + q4.y * k4.y + q4.z * k4.z + q4.w * k4.w;
            p += __shfl_xor_sync(0xFFFFFFFFu, p, 1);
            p += __shfl_xor_sync(0xFFFFFFFFu, p, 2);
            float w = __expf(p * 0.25f);
            if ((lane & 3) == 0) hsum += w;
            a.x += w * v4.x;
            a.y += w * v4.y;
            a.z += w * v4.z;
            a.w += w * v4.w;
        }
        ((float4*)g_acc)[n * 32 + lane] = a;
    }
    if ((lane & 3) == 0) g_partial[warp * 8 + h] = hsum;
}

// ======================================================================
// Deterministic denominator reduction: 1 block, fixed summation order.
// ======================================================================
__global__ void denom_kernel()
{
    __shared__ float sh[256];
    const int t = threadIdx.x;
    const int h = t & 7;
    const int i0 = t >> 3;
    float s = 0.f;
    for (int i = i0; i < TOTAL_WARPS; i += 32)
        s += g_partial[i * 8 + h];
    sh[t] = s;
    __syncthreads();
    if (t < 8) {
        float tot = 0.f;
        #pragma unroll
        for (int j = 0; j < 32; j++) tot += sh[t + j * 8];
        g_inv_denom[t] = 1.0f / tot;
    }
}

// ======================================================================
// kernel_launch
// ======================================================================
extern "C" void kernel_launch(void* const* d_in, const int* in_sizes, int n_in,
                              void* d_out, int out_size)
{
    const float* feat = (const float*)d_in[0];
    const void*  ei   = d_in[1];
    const float* Wq   = (const float*)d_in[2];
    const float* bq   = (const float*)d_in[3];
    const float* Wk   = (const float*)d_in[4];
    const float* bk   = (const float*)d_in[5];
    const float* Wv   = (const float*)d_in[6];
    const float* bv   = (const float*)d_in[7];
    const float* Wo   = (const float*)d_in[8];
    const float* bo   = (const float*)d_in[9];
    float* out = (float*)d_out;

    cudaFuncSetAttribute(gemm_qkv_kernel,
                         cudaFuncAttributeMaxDynamicSharedMemorySize, SM_TOTAL);
    cudaFuncSetAttribute(gemm_mma_kernel,
                         cudaFuncAttributeMaxDynamicSharedMemorySize, SM_TOTAL);

    float* q;   cudaGetSymbolAddress((void**)&q,   g_q);
    float* k;   cudaGetSymbolAddress((void**)&k,   g_k);
    float* v;   cudaGetSymbolAddress((void**)&v,   g_v);
    float* acc; cudaGetSymbolAddress((void**)&acc, g_acc);
    float* inv; cudaGetSymbolAddress((void**)&inv, g_inv_denom);

    const int gemm_blocks = (NN + 127) / 128;  // 782

    detect_kernel<<<1, 1>>>((const int*)ei);
    zero_hist_kernel<<<391, 256>>>();
    count_kernel<<<1280, 256>>>(ei);
    scan_kernel<<<1, 1024>>>();
    fill_kernel<<<1280, 256>>>(ei);

    gemm_qkv_kernel<<<gemm_blocks, 256, SM_TOTAL>>>(feat,
                                                    Wq, bq, q,
                                                    Wk, bk, k,
                                                    Wv, bv, v);

    gather_kernel<<<GATHER_BLOCKS, GATHER_THREADS>>>();
    denom_kernel<<<1, 256>>>();

    gemm_mma_kernel<<<gemm_blocks, 256, SM_TOTAL>>>(acc, Wo, bo, out, inv);
}

// round 8
// speedup vs baseline: 2.2585x; 1.2376x over previous
#include <cuda_runtime.h>
#include <cuda_bf16.h>
#include <cstdint>

// Problem constants
#define NN 100000
#define CC 128
#define HH 8
#define DD 16
#define EE 640000

// -------- device scratch (static; no runtime allocation allowed) --------
__device__ float g_q[NN * CC];
__device__ float g_k[NN * CC];
__device__ float g_v[NN * CC];
__device__ float g_acc[NN * CC];
__device__ int   g_hist[NN];
__device__ int   g_cursor[NN];
__device__ int   g_rowptr[NN + 1];
__device__ int   g_ecol[EE];

#define SCAN_CHUNK 1024
#define SCAN_BLOCKS ((NN + SCAN_CHUNK - 1) / SCAN_CHUNK)   // 98
__device__ int g_bsum[SCAN_BLOCKS];
__device__ int g_boff[SCAN_BLOCKS];

#define GATHER_BLOCKS 512
#define GATHER_THREADS 256
#define TOTAL_WARPS (GATHER_BLOCKS * GATHER_THREADS / 32)   // 4096
__device__ float g_partial[TOTAL_WARPS * HH];
__device__ float g_inv_denom[HH];
__device__ int   g_is32;             // 1 if edge_index is int32, 0 if int64

// ======================================================================
// Detect edge_index dtype (int32 vs int64)
// ======================================================================
__global__ void detect_kernel(const int* __restrict__ ei_words)
{
    int any = 0;
    #pragma unroll
    for (int i = 0; i < 64; i++)
        any |= ei_words[2 * i + 1];
    g_is32 = (any != 0) ? 1 : 0;
}

__device__ __forceinline__ void load_edge(const void* ei, int is32, int e,
                                          int& row, int& col)
{
    if (is32) {
        row = ((const int*)ei)[e];
        col = ((const int*)ei)[EE + e];
    } else {
        row = (int)((const long long*)ei)[e];
        col = (int)((const long long*)ei)[EE + e];
    }
    if ((unsigned)row >= NN) row = 0;
    if ((unsigned)col >= NN) col = 0;
}

// ======================================================================
// CSR build: zero -> count -> scan(3-phase) -> fill
// ======================================================================
__global__ void zero_hist_kernel()
{
    for (int i = blockIdx.x * blockDim.x + threadIdx.x; i < NN;
         i += gridDim.x * blockDim.x) {
        g_hist[i] = 0;
        g_cursor[i] = 0;
    }
}

__global__ void count_kernel(const void* __restrict__ ei)
{
    const int is32 = g_is32;
    for (int e = blockIdx.x * blockDim.x + threadIdx.x; e < EE;
         e += gridDim.x * blockDim.x) {
        int row, col;
        load_edge(ei, is32, e, row, col);
        atomicAdd(&g_hist[row], 1);
    }
}

// Phase 1: per-chunk local exclusive prefix + chunk total
__global__ __launch_bounds__(256) void scan1_kernel()
{
    __shared__ int sh[256];
    const int b = blockIdx.x;
    const int t = threadIdx.x;
    const int base = b * SCAN_CHUNK + t * 4;
    int v[4];
    int s = 0;
    #pragma unroll
    for (int j = 0; j < 4; j++) {
        int idx = base + j;
        v[j] = (idx < NN) ? g_hist[idx] : 0;
        s += v[j];
    }
    sh[t] = s;
    __syncthreads();
    #pragma unroll
    for (int off = 1; off < 256; off <<= 1) {
        int x = (t >= off) ? sh[t - off] : 0;
        __syncthreads();
        sh[t] += x;
        __syncthreads();
    }
    int excl = (t == 0) ? 0 : sh[t - 1];
    #pragma unroll
    for (int j = 0; j < 4; j++) {
        int idx = base + j;
        if (idx < NN) g_rowptr[idx] = excl;
        excl += v[j];
    }
    if (t == 255) g_bsum[b] = sh[255];
}

// Phase 2: scan chunk totals (1 block)
__global__ __launch_bounds__(128) void scan2_kernel()
{
    __shared__ int sh[128];
    const int t = threadIdx.x;
    sh[t] = (t < SCAN_BLOCKS) ? g_bsum[t] : 0;
    __syncthreads();
    #pragma unroll
    for (int off = 1; off < 128; off <<= 1) {
        int x = (t >= off) ? sh[t - off] : 0;
        __syncthreads();
        sh[t] += x;
        __syncthreads();
    }
    if (t < SCAN_BLOCKS) g_boff[t] = (t == 0) ? 0 : sh[t - 1];
    if (t == 127) g_rowptr[NN] = sh[127];
}

// Phase 3: add chunk offsets
__global__ __launch_bounds__(256) void scan3_kernel()
{
    const int b = blockIdx.x;
    const int off = g_boff[b];
    const int base = b * SCAN_CHUNK + threadIdx.x * 4;
    #pragma unroll
    for (int j = 0; j < 4; j++) {
        int idx = base + j;
        if (idx < NN) g_rowptr[idx] += off;
    }
}

__global__ void fill_kernel(const void* __restrict__ ei)
{
    const int is32 = g_is32;
    for (int e = blockIdx.x * blockDim.x + threadIdx.x; e < EE;
         e += gridDim.x * blockDim.x) {
        int row, col;
        load_edge(ei, is32, e, row, col);
        int slot = atomicAdd(&g_cursor[row], 1);
        g_ecol[g_rowptr[row] + slot] = col;
    }
}

// ======================================================================
// mma.sync helpers
// ======================================================================
__device__ __forceinline__ uint32_t smem_u32(const void* p) {
    uint32_t a;
    asm("{ .reg .u64 t; cvta.to.shared.u64 t, %1; cvt.u32.u64 %0, t; }"
        : "=r"(a) : "l"(p));
    return a;
}
__device__ __forceinline__ void ldsm_x4(uint32_t addr, uint32_t& r0, uint32_t& r1,
                                        uint32_t& r2, uint32_t& r3) {
    asm volatile("ldmatrix.sync.aligned.m8n8.x4.shared.b16 {%0,%1,%2,%3}, [%4];"
                 : "=r"(r0), "=r"(r1), "=r"(r2), "=r"(r3) : "r"(addr));
}
__device__ __forceinline__ void ldsm_x2(uint32_t addr, uint32_t& r0, uint32_t& r1) {
    asm volatile("ldmatrix.sync.aligned.m8n8.x2.shared.b16 {%0,%1}, [%2];"
                 : "=r"(r0), "=r"(r1) : "r"(addr));
}
__device__ __forceinline__ void mma16816(float* c, const uint32_t* a,
                                         const uint32_t* b) {
    asm volatile(
        "mma.sync.aligned.m16n8k16.row.col.f32.bf16.bf16.f32 "
        "{%0,%1,%2,%3}, {%4,%5,%6,%7}, {%8,%9}, {%0,%1,%2,%3};"
        : "+f"(c[0]), "+f"(c[1]), "+f"(c[2]), "+f"(c[3])
        : "r"(a[0]), "r"(a[1]), "r"(a[2]), "r"(a[3]), "r"(b[0]), "r"(b[1]));
}

// ======================================================================
// GEMM building blocks (bf16 2-way split, fp32 accumulate)
// Tile: 128 rows x 128 cols, 256 threads (8 warps, 4x2).
// ======================================================================
#define TSTRIDE 136
#define TILE_BF16 (128 * TSTRIDE)
#define SM_TOTAL (4 * TILE_BF16 * 2)

__device__ __forceinline__ void split_store(__nv_bfloat16* hi, __nv_bfloat16* lo,
                                            int off, float4 v) {
    #pragma unroll
    for (int j = 0; j < 4; j++) {
        float x = (j == 0) ? v.x : (j == 1) ? v.y : (j == 2) ? v.z : v.w;
        __nv_bfloat16 h = __float2bfloat16(x);
        hi[off + j] = h;
        lo[off + j] = __float2bfloat16(x - __bfloat162float(h));
    }
}

__device__ __forceinline__ void conv_w(const float* __restrict__ W,
                                       __nv_bfloat16* w_hi, __nv_bfloat16* w_lo,
                                       int tid) {
    #pragma unroll
    for (int i = 0; i < 16; i++) {
        int f  = tid + i * 256;
        int r  = f >> 5;
        int c4 = f & 31;
        float4 vw = ((const float4*)W)[r * 32 + c4];
        split_store(w_hi, w_lo, r * TSTRIDE + c4 * 4, vw);
    }
}

__device__ __forceinline__ void mma_compute_store(
    const __nv_bfloat16* a_hi, const __nv_bfloat16* a_lo,
    const __nv_bfloat16* w_hi, const __nv_bfloat16* w_lo,
    const float* __restrict__ bias, float* __restrict__ out,
    int row0, int wid, int lane)
{
    const int m_warp = (wid >> 1) * 32;
    const int n_warp = (wid & 1) * 64;
    const uint32_t aH_base = smem_u32(a_hi);
    const uint32_t aL_base = smem_u32(a_lo);
    const uint32_t wH_base = smem_u32(w_hi);
    const uint32_t wL_base = smem_u32(w_lo);
    const uint32_t a_lane_off =
        (uint32_t)(((lane & 15)) * TSTRIDE + 8 * (lane >> 4)) * 2;
    const uint32_t b_lane_off =
        (uint32_t)(((lane & 7)) * TSTRIDE + 8 * ((lane >> 3) & 1)) * 2;

    float acc[2][8][4];
    #pragma unroll
    for (int mt = 0; mt < 2; mt++)
        #pragma unroll
        for (int nt = 0; nt < 8; nt++)
            #pragma unroll
            for (int j = 0; j < 4; j++) acc[mt][nt][j] = 0.f;

    #pragma unroll
    for (int kt = 0; kt < 8; kt++) {
        const uint32_t koff = kt * 32;
        uint32_t aH[2][4], aL[2][4];
        #pragma unroll
        for (int mt = 0; mt < 2; mt++) {
            uint32_t ra = (uint32_t)((m_warp + mt * 16) * TSTRIDE * 2) + a_lane_off + koff;
            ldsm_x4(aH_base + ra, aH[mt][0], aH[mt][1], aH[mt][2], aH[mt][3]);
            ldsm_x4(aL_base + ra, aL[mt][0], aL[mt][1], aL[mt][2], aL[mt][3]);
        }
        #pragma unroll
        for (int nt = 0; nt < 8; nt++) {
            uint32_t rb = (uint32_t)((n_warp + nt * 8) * TSTRIDE * 2) + b_lane_off + koff;
            uint32_t bH[2], bL[2];
            ldsm_x2(wH_base + rb, bH[0], bH[1]);
            ldsm_x2(wL_base + rb, bL[0], bL[1]);
            #pragma unroll
            for (int mt = 0; mt < 2; mt++) {
                mma16816(acc[mt][nt], aH[mt], bH);
                mma16816(acc[mt][nt], aH[mt], bL);
                mma16816(acc[mt][nt], aL[mt], bH);
            }
        }
    }

    const int qrow = lane >> 2;
    const int qcol = (lane & 3) * 2;
    #pragma unroll
    for (int mt = 0; mt < 2; mt++) {
        #pragma unroll
        for (int half = 0; half < 2; half++) {
            int grow = row0 + m_warp + mt * 16 + qrow + half * 8;
            if (grow < NN) {
                #pragma unroll
                for (int nt = 0; nt < 8; nt++) {
                    int col = n_warp + nt * 8 + qcol;
                    float2 o;
                    o.x = acc[mt][nt][half * 2 + 0] + __ldg(&bias[col]);
                    o.y = acc[mt][nt][half * 2 + 1] + __ldg(&bias[col + 1]);
                    *(float2*)&out[grow * 128 + col] = o;
                }
            }
        }
    }
}

// Fused Q/K/V GEMM: load+convert feat tile once, 3 weights
__global__ __launch_bounds__(256) void gemm_qkv_kernel(
    const float* __restrict__ A,
    const float* __restrict__ Wq, const float* __restrict__ bq, float* __restrict__ oq,
    const float* __restrict__ Wk, const float* __restrict__ bk, float* __restrict__ ok,
    const float* __restrict__ Wv, const float* __restrict__ bv, float* __restrict__ ov)
{
    extern __shared__ __nv_bfloat16 smem[];
    __nv_bfloat16* a_hi = smem;
    __nv_bfloat16* a_lo = smem + TILE_BF16;
    __nv_bfloat16* w_hi = smem + 2 * TILE_BF16;
    __nv_bfloat16* w_lo = smem + 3 * TILE_BF16;

    const int tid  = threadIdx.x;
    const int wid  = tid >> 5;
    const int lane = tid & 31;
    const int row0 = blockIdx.x * 128;

    #pragma unroll
    for (int i = 0; i < 16; i++) {
        int f  = tid + i * 256;
        int r  = f >> 5;
        int c4 = f & 31;
        float4 va = make_float4(0.f, 0.f, 0.f, 0.f);
        int gr = row0 + r;
        if (gr < NN) va = ((const float4*)A)[gr * 32 + c4];
        split_store(a_hi, a_lo, r * TSTRIDE + c4 * 4, va);
    }

    const float* Ws[3] = {Wq, Wk, Wv};
    const float* bs[3] = {bq, bk, bv};
    float*       os[3] = {oq, ok, ov};
    #pragma unroll 1
    for (int w = 0; w < 3; w++) {
        conv_w(Ws[w], w_hi, w_lo, tid);
        __syncthreads();
        mma_compute_store(a_hi, a_lo, w_hi, w_lo, bs[w], os[w], row0, wid, lane);
        __syncthreads();
    }
}

// Single GEMM with optional per-head column scale on A (for final Wo GEMM)
__global__ __launch_bounds__(256) void gemm_mma_kernel(
    const float* __restrict__ A,
    const float* __restrict__ W,
    const float* __restrict__ bias,
    float* __restrict__ out,
    const float* __restrict__ colscale)
{
    extern __shared__ __nv_bfloat16 smem[];
    __nv_bfloat16* a_hi = smem;
    __nv_bfloat16* a_lo = smem + TILE_BF16;
    __nv_bfloat16* w_hi = smem + 2 * TILE_BF16;
    __nv_bfloat16* w_lo = smem + 3 * TILE_BF16;

    const int tid  = threadIdx.x;
    const int wid  = tid >> 5;
    const int lane = tid & 31;
    const int row0 = blockIdx.x * 128;

    #pragma unroll
    for (int i = 0; i < 16; i++) {
        int f  = tid + i * 256;
        int r  = f >> 5;
        int c4 = f & 31;
        float4 va = make_float4(0.f, 0.f, 0.f, 0.f);
        int gr = row0 + r;
        if (gr < NN) va = ((const float4*)A)[gr * 32 + c4];
        if (colscale) {
            float sc = __ldg(&colscale[c4 >> 2]);   // head = (c4*4)/16
            va.x *= sc; va.y *= sc; va.z *= sc; va.w *= sc;
        }
        split_store(a_hi, a_lo, r * TSTRIDE + c4 * 4, va);
    }
    conv_w(W, w_hi, w_lo, tid);
    __syncthreads();
    mma_compute_store(a_hi, a_lo, w_hi, w_lo, bias, out, row0, wid, lane);
}

// ======================================================================
// Gather: one warp per node. Unnormalized accumulate + denom partials.
// ======================================================================
__global__ __launch_bounds__(GATHER_THREADS) void gather_kernel()
{
    const int lane = threadIdx.x & 31;
    const int warp = (blockIdx.x * blockDim.x + threadIdx.x) >> 5;
    const int h = lane >> 2;
    float hsum = 0.f;

    for (int n = warp; n < NN; n += TOTAL_WARPS) {
        float4 q4 = ((const float4*)g_q)[n * 32 + lane];
        float4 a = make_float4(0.f, 0.f, 0.f, 0.f);
        const int beg = g_rowptr[n];
        const int end = g_rowptr[n + 1];
        for (int j = beg; j < end; j++) {
            int col = g_ecol[j];
            float4 k4 = ((const float4*)g_k)[col * 32 + lane];
            float4 v4 = ((const float4*)g_v)[col * 32 + lane];
            float p = q4.x * k4.x + q4.y * k4.y + q4.z * k4.z + q4.w * k4.w;
            p += __shfl_xor_sync(0xFFFFFFFFu, p, 1);
            p += __shfl_xor_sync(0xFFFFFFFFu, p, 2);
            float w = __expf(p * 0.25f);
            if ((lane & 3) == 0) hsum += w;
            a.x += w * v4.x;
            a.y += w * v4.y;
            a.z += w * v4.z;
            a.w += w * v4.w;
        }
        ((float4*)g_acc)[n * 32 + lane] = a;
    }
    if ((lane & 3) == 0) g_partial[warp * 8 + h] = hsum;
}

// ======================================================================
// Deterministic denominator reduction: 1 block, fixed summation order.
// ======================================================================
__global__ void denom_kernel()
{
    __shared__ float sh[256];
    const int t = threadIdx.x;
    const int h = t & 7;
    const int i0 = t >> 3;
    float s = 0.f;
    for (int i = i0; i < TOTAL_WARPS; i += 32)
        s += g_partial[i * 8 + h];
    sh[t] = s;
    __syncthreads();
    if (t < 8) {
        float tot = 0.f;
        #pragma unroll
        for (int j = 0; j < 32; j++) tot += sh[t + j * 8];
        g_inv_denom[t] = 1.0f / tot;
    }
}

// ======================================================================
// kernel_launch
// ======================================================================
extern "C" void kernel_launch(void* const* d_in, const int* in_sizes, int n_in,
                              void* d_out, int out_size)
{
    const float* feat = (const float*)d_in[0];
    const void*  ei   = d_in[1];
    const float* Wq   = (const float*)d_in[2];
    const float* bq   = (const float*)d_in[3];
    const float* Wk   = (const float*)d_in[4];
    const float* bk   = (const float*)d_in[5];
    const float* Wv   = (const float*)d_in[6];
    const float* bv   = (const float*)d_in[7];
    const float* Wo   = (const float*)d_in[8];
    const float* bo   = (const float*)d_in[9];
    float* out = (float*)d_out;

    cudaFuncSetAttribute(gemm_qkv_kernel,
                         cudaFuncAttributeMaxDynamicSharedMemorySize, SM_TOTAL);
    cudaFuncSetAttribute(gemm_mma_kernel,
                         cudaFuncAttributeMaxDynamicSharedMemorySize, SM_TOTAL);

    float* q;   cudaGetSymbolAddress((void**)&q,   g_q);
    float* k;   cudaGetSymbolAddress((void**)&k,   g_k);
    float* v;   cudaGetSymbolAddress((void**)&v,   g_v);
    float* acc; cudaGetSymbolAddress((void**)&acc, g_acc);
    float* inv; cudaGetSymbolAddress((void**)&inv, g_inv_denom);

    const int gemm_blocks = (NN + 127) / 128;  // 782

    detect_kernel<<<1, 1>>>((const int*)ei);
    zero_hist_kernel<<<391, 256>>>();
    count_kernel<<<1280, 256>>>(ei);
    scan1_kernel<<<SCAN_BLOCKS, 256>>>();
    scan2_kernel<<<1, 128>>>();
    scan3_kernel<<<SCAN_BLOCKS, 256>>>();
    fill_kernel<<<1280, 256>>>(ei);

    gemm_qkv_kernel<<<gemm_blocks, 256, SM_TOTAL>>>(feat,
                                                    Wq, bq, q,
                                                    Wk, bk, k,
                                                    Wv, bv, v);

    gather_kernel<<<GATHER_BLOCKS, GATHER_THREADS>>>();
    denom_kernel<<<1, 256>>>();

    gemm_mma_kernel<<<gemm_blocks, 256, SM_TOTAL>>>(acc, Wo, bo, out, inv);
}

// round 9
// speedup vs baseline: 2.4635x; 1.0907x over previous
#include <cuda_runtime.h>
#include <cuda_bf16.h>
#include <cstdint>

// Problem constants
#define NN 100000
#define CC 128
#define HH 8
#define DD 16
#define EE 640000

// -------- device scratch (static; no runtime allocation allowed) --------
__device__ float g_q[NN * CC];
__device__ float g_k[NN * CC];
__device__ float g_v[NN * CC];
__device__ float g_acc[NN * CC];
__device__ int   g_hist[NN];
__device__ int   g_cursor[NN];
__device__ int   g_rowptr[NN + 1];
__device__ int   g_ecol[EE];

#define SCAN_CHUNK 1024
#define SCAN_BLOCKS ((NN + SCAN_CHUNK - 1) / SCAN_CHUNK)   // 98
__device__ int g_bsum[SCAN_BLOCKS];
__device__ int g_boff[SCAN_BLOCKS];

#define GATHER_BLOCKS 512
#define GATHER_THREADS 256
#define TOTAL_WARPS (GATHER_BLOCKS * GATHER_THREADS / 32)   // 4096
__device__ float g_partial[TOTAL_WARPS * HH];
__device__ float g_inv_denom[HH];
__device__ int   g_is32;             // 1 if edge_index is int32, 0 if int64

// ======================================================================
// Detect edge_index dtype (int32 vs int64)
// ======================================================================
__global__ void detect_kernel(const int* __restrict__ ei_words)
{
    int any = 0;
    #pragma unroll
    for (int i = 0; i < 64; i++)
        any |= ei_words[2 * i + 1];
    g_is32 = (any != 0) ? 1 : 0;
}

__device__ __forceinline__ void load_edge(const void* ei, int is32, int e,
                                          int& row, int& col)
{
    if (is32) {
        row = ((const int*)ei)[e];
        col = ((const int*)ei)[EE + e];
    } else {
        row = (int)((const long long*)ei)[e];
        col = (int)((const long long*)ei)[EE + e];
    }
    if ((unsigned)row >= NN) row = 0;
    if ((unsigned)col >= NN) col = 0;
}

// ======================================================================
// CSR build: zero -> count -> scan(3-phase) -> fill
// ======================================================================
__global__ void zero_hist_kernel()
{
    for (int i = blockIdx.x * blockDim.x + threadIdx.x; i < NN;
         i += gridDim.x * blockDim.x) {
        g_hist[i] = 0;
        g_cursor[i] = 0;
    }
}

__global__ void count_kernel(const void* __restrict__ ei)
{
    const int is32 = g_is32;
    for (int e = blockIdx.x * blockDim.x + threadIdx.x; e < EE;
         e += gridDim.x * blockDim.x) {
        int row, col;
        load_edge(ei, is32, e, row, col);
        atomicAdd(&g_hist[row], 1);
    }
}

__global__ __launch_bounds__(256) void scan1_kernel()
{
    __shared__ int sh[256];
    const int b = blockIdx.x;
    const int t = threadIdx.x;
    const int base = b * SCAN_CHUNK + t * 4;
    int v[4];
    int s = 0;
    #pragma unroll
    for (int j = 0; j < 4; j++) {
        int idx = base + j;
        v[j] = (idx < NN) ? g_hist[idx] : 0;
        s += v[j];
    }
    sh[t] = s;
    __syncthreads();
    #pragma unroll
    for (int off = 1; off < 256; off <<= 1) {
        int x = (t >= off) ? sh[t - off] : 0;
        __syncthreads();
        sh[t] += x;
        __syncthreads();
    }
    int excl = (t == 0) ? 0 : sh[t - 1];
    #pragma unroll
    for (int j = 0; j < 4; j++) {
        int idx = base + j;
        if (idx < NN) g_rowptr[idx] = excl;
        excl += v[j];
    }
    if (t == 255) g_bsum[b] = sh[255];
}

__global__ __launch_bounds__(128) void scan2_kernel()
{
    __shared__ int sh[128];
    const int t = threadIdx.x;
    sh[t] = (t < SCAN_BLOCKS) ? g_bsum[t] : 0;
    __syncthreads();
    #pragma unroll
    for (int off = 1; off < 128; off <<= 1) {
        int x = (t >= off) ? sh[t - off] : 0;
        __syncthreads();
        sh[t] += x;
        __syncthreads();
    }
    if (t < SCAN_BLOCKS) g_boff[t] = (t == 0) ? 0 : sh[t - 1];
    if (t == 127) g_rowptr[NN] = sh[127];
}

__global__ __launch_bounds__(256) void scan3_kernel()
{
    const int b = blockIdx.x;
    const int off = g_boff[b];
    const int base = b * SCAN_CHUNK + threadIdx.x * 4;
    #pragma unroll
    for (int j = 0; j < 4; j++) {
        int idx = base + j;
        if (idx < NN) g_rowptr[idx] += off;
    }
}

__global__ void fill_kernel(const void* __restrict__ ei)
{
    const int is32 = g_is32;
    for (int e = blockIdx.x * blockDim.x + threadIdx.x; e < EE;
         e += gridDim.x * blockDim.x) {
        int row, col;
        load_edge(ei, is32, e, row, col);
        int slot = atomicAdd(&g_cursor[row], 1);
        g_ecol[g_rowptr[row] + slot] = col;
    }
}

// ======================================================================
// mma.sync helpers
// ======================================================================
__device__ __forceinline__ uint32_t smem_u32(const void* p) {
    uint32_t a;
    asm("{ .reg .u64 t; cvta.to.shared.u64 t, %1; cvt.u32.u64 %0, t; }"
        : "=r"(a) : "l"(p));
    return a;
}
__device__ __forceinline__ void ldsm_x4(uint32_t addr, uint32_t& r0, uint32_t& r1,
                                        uint32_t& r2, uint32_t& r3) {
    asm volatile("ldmatrix.sync.aligned.m8n8.x4.shared.b16 {%0,%1,%2,%3}, [%4];"
                 : "=r"(r0), "=r"(r1), "=r"(r2), "=r"(r3) : "r"(addr));
}
__device__ __forceinline__ void ldsm_x2(uint32_t addr, uint32_t& r0, uint32_t& r1) {
    asm volatile("ldmatrix.sync.aligned.m8n8.x2.shared.b16 {%0,%1}, [%2];"
                 : "=r"(r0), "=r"(r1) : "r"(addr));
}
__device__ __forceinline__ void mma16816(float* c, const uint32_t* a,
                                         const uint32_t* b) {
    asm volatile(
        "mma.sync.aligned.m16n8k16.row.col.f32.bf16.bf16.f32 "
        "{%0,%1,%2,%3}, {%4,%5,%6,%7}, {%8,%9}, {%0,%1,%2,%3};"
        : "+f"(c[0]), "+f"(c[1]), "+f"(c[2]), "+f"(c[3])
        : "r"(a[0]), "r"(a[1]), "r"(a[2]), "r"(a[3]), "r"(b[0]), "r"(b[1]));
}

// ======================================================================
// GEMM building blocks (bf16 2-way split, fp32 accumulate)
// Tile: 64 rows x 128 cols, 256 threads (8 warps, 2x4).
// smem ~102 KB -> 2 CTAs/SM for phase overlap.
// ======================================================================
#define TSTRIDE 136
#define A_TILE_ELEMS (64 * TSTRIDE)
#define W_TILE_ELEMS (128 * TSTRIDE)
#define SM_TOTAL ((2 * A_TILE_ELEMS + 2 * W_TILE_ELEMS) * 2)

__device__ __forceinline__ void split_store(__nv_bfloat16* hi, __nv_bfloat16* lo,
                                            int off, float4 v) {
    #pragma unroll
    for (int j = 0; j < 4; j++) {
        float x = (j == 0) ? v.x : (j == 1) ? v.y : (j == 2) ? v.z : v.w;
        __nv_bfloat16 h = __float2bfloat16(x);
        hi[off + j] = h;
        lo[off + j] = __float2bfloat16(x - __bfloat162float(h));
    }
}

// Convert W[128x128] into wH/wL smem tiles
__device__ __forceinline__ void conv_w(const float* __restrict__ W,
                                       __nv_bfloat16* w_hi, __nv_bfloat16* w_lo,
                                       int tid) {
    #pragma unroll
    for (int i = 0; i < 16; i++) {
        int f  = tid + i * 256;
        int r  = f >> 5;
        int c4 = f & 31;
        float4 vw = ((const float4*)W)[r * 32 + c4];
        split_store(w_hi, w_lo, r * TSTRIDE + c4 * 4, vw);
    }
}

// Load + convert 64-row A tile (guarded, optional per-head column scale)
__device__ __forceinline__ void conv_a64(const float* __restrict__ A,
                                         const float* __restrict__ colscale,
                                         __nv_bfloat16* a_hi, __nv_bfloat16* a_lo,
                                         int row0, int tid) {
    #pragma unroll
    for (int i = 0; i < 8; i++) {
        int f  = tid + i * 256;     // float4 index 0..2047
        int r  = f >> 5;            // 0..63
        int c4 = f & 31;
        float4 va = make_float4(0.f, 0.f, 0.f, 0.f);
        int gr = row0 + r;
        if (gr < NN) va = ((const float4*)A)[gr * 32 + c4];
        if (colscale) {
            float sc = __ldg(&colscale[c4 >> 2]);   // head = (c4*4)/16
            va.x *= sc; va.y *= sc; va.z *= sc; va.w *= sc;
        }
        split_store(a_hi, a_lo, r * TSTRIDE + c4 * 4, va);
    }
}

// MMA compute + epilogue, 64x128 tile, warp grid 2(m) x 4(n)
__device__ __forceinline__ void mma_compute_store(
    const __nv_bfloat16* a_hi, const __nv_bfloat16* a_lo,
    const __nv_bfloat16* w_hi, const __nv_bfloat16* w_lo,
    const float* __restrict__ bias, float* __restrict__ out,
    int row0, int wid, int lane)
{
    const int m_warp = (wid >> 2) * 32;   // 0 or 32
    const int n_warp = (wid & 3) * 32;    // 0,32,64,96
    const uint32_t aH_base = smem_u32(a_hi);
    const uint32_t aL_base = smem_u32(a_lo);
    const uint32_t wH_base = smem_u32(w_hi);
    const uint32_t wL_base = smem_u32(w_lo);
    const uint32_t a_lane_off =
        (uint32_t)(((lane & 15)) * TSTRIDE + 8 * (lane >> 4)) * 2;
    const uint32_t b_lane_off =
        (uint32_t)(((lane & 7)) * TSTRIDE + 8 * ((lane >> 3) & 1)) * 2;

    float acc[2][4][4];
    #pragma unroll
    for (int mt = 0; mt < 2; mt++)
        #pragma unroll
        for (int nt = 0; nt < 4; nt++)
            #pragma unroll
            for (int j = 0; j < 4; j++) acc[mt][nt][j] = 0.f;

    #pragma unroll
    for (int kt = 0; kt < 8; kt++) {
        const uint32_t koff = kt * 32;   // 16 bf16 = 32 bytes
        uint32_t aH[2][4], aL[2][4];
        #pragma unroll
        for (int mt = 0; mt < 2; mt++) {
            uint32_t ra = (uint32_t)((m_warp + mt * 16) * TSTRIDE * 2) + a_lane_off + koff;
            ldsm_x4(aH_base + ra, aH[mt][0], aH[mt][1], aH[mt][2], aH[mt][3]);
            ldsm_x4(aL_base + ra, aL[mt][0], aL[mt][1], aL[mt][2], aL[mt][3]);
        }
        #pragma unroll
        for (int nt = 0; nt < 4; nt++) {
            uint32_t rb = (uint32_t)((n_warp + nt * 8) * TSTRIDE * 2) + b_lane_off + koff;
            uint32_t bH[2], bL[2];
            ldsm_x2(wH_base + rb, bH[0], bH[1]);
            ldsm_x2(wL_base + rb, bL[0], bL[1]);
            #pragma unroll
            for (int mt = 0; mt < 2; mt++) {
                mma16816(acc[mt][nt], aH[mt], bH);
                mma16816(acc[mt][nt], aH[mt], bL);
                mma16816(acc[mt][nt], aL[mt], bH);
            }
        }
    }

    const int qrow = lane >> 2;
    const int qcol = (lane & 3) * 2;
    #pragma unroll
    for (int mt = 0; mt < 2; mt++) {
        #pragma unroll
        for (int half = 0; half < 2; half++) {
            int grow = row0 + m_warp + mt * 16 + qrow + half * 8;
            if (grow < NN) {
                #pragma unroll
                for (int nt = 0; nt < 4; nt++) {
                    int col = n_warp + nt * 8 + qcol;
                    float2 o;
                    o.x = acc[mt][nt][half * 2 + 0] + __ldg(&bias[col]);
                    o.y = acc[mt][nt][half * 2 + 1] + __ldg(&bias[col + 1]);
                    *(float2*)&out[grow * 128 + col] = o;
                }
            }
        }
    }
}

// Fused Q/K/V GEMM: load+convert feat tile once, 3 weights
__global__ __launch_bounds__(256) void gemm_qkv_kernel(
    const float* __restrict__ A,
    const float* __restrict__ Wq, const float* __restrict__ bq, float* __restrict__ oq,
    const float* __restrict__ Wk, const float* __restrict__ bk, float* __restrict__ ok,
    const float* __restrict__ Wv, const float* __restrict__ bv, float* __restrict__ ov)
{
    extern __shared__ __nv_bfloat16 smem[];
    __nv_bfloat16* a_hi = smem;
    __nv_bfloat16* a_lo = smem + A_TILE_ELEMS;
    __nv_bfloat16* w_hi = smem + 2 * A_TILE_ELEMS;
    __nv_bfloat16* w_lo = smem + 2 * A_TILE_ELEMS + W_TILE_ELEMS;

    const int tid  = threadIdx.x;
    const int wid  = tid >> 5;
    const int lane = tid & 31;
    const int row0 = blockIdx.x * 64;

    conv_a64(A, (const float*)0, a_hi, a_lo, row0, tid);

    const float* Ws[3] = {Wq, Wk, Wv};
    const float* bs[3] = {bq, bk, bv};
    float*       os[3] = {oq, ok, ov};
    #pragma unroll 1
    for (int w = 0; w < 3; w++) {
        conv_w(Ws[w], w_hi, w_lo, tid);
        __syncthreads();
        mma_compute_store(a_hi, a_lo, w_hi, w_lo, bs[w], os[w], row0, wid, lane);
        __syncthreads();
    }
}

// Single GEMM with optional per-head column scale on A (final Wo GEMM)
__global__ __launch_bounds__(256) void gemm_mma_kernel(
    const float* __restrict__ A,
    const float* __restrict__ W,
    const float* __restrict__ bias,
    float* __restrict__ out,
    const float* __restrict__ colscale)
{
    extern __shared__ __nv_bfloat16 smem[];
    __nv_bfloat16* a_hi = smem;
    __nv_bfloat16* a_lo = smem + A_TILE_ELEMS;
    __nv_bfloat16* w_hi = smem + 2 * A_TILE_ELEMS;
    __nv_bfloat16* w_lo = smem + 2 * A_TILE_ELEMS + W_TILE_ELEMS;

    const int tid  = threadIdx.x;
    const int wid  = tid >> 5;
    const int lane = tid & 31;
    const int row0 = blockIdx.x * 64;

    conv_a64(A, colscale, a_hi, a_lo, row0, tid);
    conv_w(W, w_hi, w_lo, tid);
    __syncthreads();
    mma_compute_store(a_hi, a_lo, w_hi, w_lo, bias, out, row0, wid, lane);
}

// ======================================================================
// Gather: one warp per node; next-col prefetch breaks the load chain.
// ======================================================================
__global__ __launch_bounds__(GATHER_THREADS) void gather_kernel()
{
    const int lane = threadIdx.x & 31;
    const int warp = (blockIdx.x * blockDim.x + threadIdx.x) >> 5;
    const int h = lane >> 2;
    float hsum = 0.f;

    for (int n = warp; n < NN; n += TOTAL_WARPS) {
        float4 q4 = ((const float4*)g_q)[n * 32 + lane];
        float4 a = make_float4(0.f, 0.f, 0.f, 0.f);
        const int beg = g_rowptr[n];
        const int end = g_rowptr[n + 1];
        int col_next = (beg < end) ? __ldg(&g_ecol[beg]) : 0;
        for (int j = beg; j < end; j++) {
            int col = col_next;
            if (j + 1 < end) col_next = __ldg(&g_ecol[j + 1]);
            float4 k4 = ((const float4*)g_k)[col * 32 + lane];
            float4 v4 = ((const float4*)g_v)[col * 32 + lane];
            float p = q4.x * k4.x + q4.y * k4.y + q4.z * k4.z + q4.w * k4.w;
            p += __shfl_xor_sync(0xFFFFFFFFu, p, 1);
            p += __shfl_xor_sync(0xFFFFFFFFu, p, 2);
            float w = __expf(p * 0.25f);
            if ((lane & 3) == 0) hsum += w;
            a.x += w * v4.x;
            a.y += w * v4.y;
            a.z += w * v4.z;
            a.w += w * v4.w;
        }
        ((float4*)g_acc)[n * 32 + lane] = a;
    }
    if ((lane & 3) == 0) g_partial[warp * 8 + h] = hsum;
}

// ======================================================================
// Deterministic denominator reduction: 1 block, fixed summation order.
// ======================================================================
__global__ void denom_kernel()
{
    __shared__ float sh[256];
    const int t = threadIdx.x;
    const int h = t & 7;
    const int i0 = t >> 3;
    float s = 0.f;
    for (int i = i0; i < TOTAL_WARPS; i += 32)
        s += g_partial[i * 8 + h];
    sh[t] = s;
    __syncthreads();
    if (t < 8) {
        float tot = 0.f;
        #pragma unroll
        for (int j = 0; j < 32; j++) tot += sh[t + j * 8];
        g_inv_denom[t] = 1.0f / tot;
    }
}

// ======================================================================
// kernel_launch
// ======================================================================
extern "C" void kernel_launch(void* const* d_in, const int* in_sizes, int n_in,
                              void* d_out, int out_size)
{
    const float* feat = (const float*)d_in[0];
    const void*  ei   = d_in[1];
    const float* Wq   = (const float*)d_in[2];
    const float* bq   = (const float*)d_in[3];
    const float* Wk   = (const float*)d_in[4];
    const float* bk   = (const float*)d_in[5];
    const float* Wv   = (const float*)d_in[6];
    const float* bv   = (const float*)d_in[7];
    const float* Wo   = (const float*)d_in[8];
    const float* bo   = (const float*)d_in[9];
    float* out = (float*)d_out;

    cudaFuncSetAttribute(gemm_qkv_kernel,
                         cudaFuncAttributeMaxDynamicSharedMemorySize, SM_TOTAL);
    cudaFuncSetAttribute(gemm_mma_kernel,
                         cudaFuncAttributeMaxDynamicSharedMemorySize, SM_TOTAL);

    float* q;   cudaGetSymbolAddress((void**)&q,   g_q);
    float* k;   cudaGetSymbolAddress((void**)&k,   g_k);
    float* v;   cudaGetSymbolAddress((void**)&v,   g_v);
    float* acc; cudaGetSymbolAddress((void**)&acc, g_acc);
    float* inv; cudaGetSymbolAddress((void**)&inv, g_inv_denom);

    const int gemm_blocks = (NN + 63) / 64;  // 1563

    detect_kernel<<<1, 1>>>((const int*)ei);
    zero_hist_kernel<<<391, 256>>>();
    count_kernel<<<1280, 256>>>(ei);
    scan1_kernel<<<SCAN_BLOCKS, 256>>>();
    scan2_kernel<<<1, 128>>>();
    scan3_kernel<<<SCAN_BLOCKS, 256>>>();
    fill_kernel<<<1280, 256>>>(ei);

    gemm_qkv_kernel<<<gemm_blocks, 256, SM_TOTAL>>>(feat,
                                                    Wq, bq, q,
                                                    Wk, bk, k,
                                                    Wv, bv, v);

    gather_kernel<<<GATHER_BLOCKS, GATHER_THREADS>>>();
    denom_kernel<<<1, 256>>>();

    gemm_mma_kernel<<<gemm_blocks, 256, SM_TOTAL>>>(acc, Wo, bo, out, inv);
}

// round 10
// speedup vs baseline: 2.9774x; 1.2086x over previous
#include <cuda_runtime.h>
#include <cuda_bf16.h>
#include <cstdint>

// Problem constants
#define NN 100000
#define CC 128
#define HH 8
#define DD 16
#define EE 640000

// -------- device scratch (static; no runtime allocation allowed) --------
__device__ float g_q[NN * CC];
__device__ float g_k[NN * CC];
__device__ float g_v[NN * CC];
__device__ float g_acc[NN * CC];
__device__ int   g_hist[NN];
__device__ int   g_cursor[NN];
__device__ int   g_rowptr[NN + 1];
__device__ int   g_ecol[EE];

// Pre-converted weights: bf16 hi/lo, row-major [4][128*128]
__device__ __nv_bfloat16 g_whi[4][CC * CC];
__device__ __nv_bfloat16 g_wlo[4][CC * CC];

#define SCAN_CHUNK 1024
#define SCAN_BLOCKS ((NN + SCAN_CHUNK - 1) / SCAN_CHUNK)   // 98
__device__ int g_bsum[SCAN_BLOCKS];
__device__ int g_boff[SCAN_BLOCKS];

#define GATHER_BLOCKS 1024
#define GATHER_THREADS 256
#define TOTAL_WARPS (GATHER_BLOCKS * GATHER_THREADS / 32)   // 8192
__device__ float g_partial[TOTAL_WARPS * HH];
__device__ float g_inv_denom[HH];
__device__ int   g_is32;             // 1 if edge_index is int32, 0 if int64

// ======================================================================
// Detect edge_index dtype (int32 vs int64)
// ======================================================================
__global__ void detect_kernel(const int* __restrict__ ei_words)
{
    int any = 0;
    #pragma unroll
    for (int i = 0; i < 64; i++)
        any |= ei_words[2 * i + 1];
    g_is32 = (any != 0) ? 1 : 0;
}

__device__ __forceinline__ void load_edge(const void* ei, int is32, int e,
                                          int& row, int& col)
{
    if (is32) {
        row = ((const int*)ei)[e];
        col = ((const int*)ei)[EE + e];
    } else {
        row = (int)((const long long*)ei)[e];
        col = (int)((const long long*)ei)[EE + e];
    }
    if ((unsigned)row >= NN) row = 0;
    if ((unsigned)col >= NN) col = 0;
}

// ======================================================================
// Pre-convert all 4 weight matrices to bf16 hi/lo (runs once per launch)
// ======================================================================
__global__ __launch_bounds__(256) void convw_kernel(
    const float* __restrict__ Wq, const float* __restrict__ Wk,
    const float* __restrict__ Wv, const float* __restrict__ Wo)
{
    const int i = blockIdx.x * blockDim.x + threadIdx.x;
    if (i >= CC * CC) return;
    const float* Ws[4] = {Wq, Wk, Wv, Wo};
    #pragma unroll
    for (int w = 0; w < 4; w++) {
        float x = Ws[w][i];
        __nv_bfloat16 h = __float2bfloat16(x);
        g_whi[w][i] = h;
        g_wlo[w][i] = __float2bfloat16(x - __bfloat162float(h));
    }
}

// ======================================================================
// CSR build: zero -> count -> scan(3-phase) -> fill
// ======================================================================
__global__ void zero_hist_kernel()
{
    for (int i = blockIdx.x * blockDim.x + threadIdx.x; i < NN;
         i += gridDim.x * blockDim.x) {
        g_hist[i] = 0;
        g_cursor[i] = 0;
    }
}

__global__ void count_kernel(const void* __restrict__ ei)
{
    const int is32 = g_is32;
    for (int e = blockIdx.x * blockDim.x + threadIdx.x; e < EE;
         e += gridDim.x * blockDim.x) {
        int row, col;
        load_edge(ei, is32, e, row, col);
        atomicAdd(&g_hist[row], 1);
    }
}

__global__ __launch_bounds__(256) void scan1_kernel()
{
    __shared__ int sh[256];
    const int b = blockIdx.x;
    const int t = threadIdx.x;
    const int base = b * SCAN_CHUNK + t * 4;
    int v[4];
    int s = 0;
    #pragma unroll
    for (int j = 0; j < 4; j++) {
        int idx = base + j;
        v[j] = (idx < NN) ? g_hist[idx] : 0;
        s += v[j];
    }
    sh[t] = s;
    __syncthreads();
    #pragma unroll
    for (int off = 1; off < 256; off <<= 1) {
        int x = (t >= off) ? sh[t - off] : 0;
        __syncthreads();
        sh[t] += x;
        __syncthreads();
    }
    int excl = (t == 0) ? 0 : sh[t - 1];
    #pragma unroll
    for (int j = 0; j < 4; j++) {
        int idx = base + j;
        if (idx < NN) g_rowptr[idx] = excl;
        excl += v[j];
    }
    if (t == 255) g_bsum[b] = sh[255];
}

__global__ __launch_bounds__(128) void scan2_kernel()
{
    __shared__ int sh[128];
    const int t = threadIdx.x;
    sh[t] = (t < SCAN_BLOCKS) ? g_bsum[t] : 0;
    __syncthreads();
    #pragma unroll
    for (int off = 1; off < 128; off <<= 1) {
        int x = (t >= off) ? sh[t - off] : 0;
        __syncthreads();
        sh[t] += x;
        __syncthreads();
    }
    if (t < SCAN_BLOCKS) g_boff[t] = (t == 0) ? 0 : sh[t - 1];
    if (t == 127) g_rowptr[NN] = sh[127];
}

__global__ __launch_bounds__(256) void scan3_kernel()
{
    const int b = blockIdx.x;
    const int off = g_boff[b];
    const int base = b * SCAN_CHUNK + threadIdx.x * 4;
    #pragma unroll
    for (int j = 0; j < 4; j++) {
        int idx = base + j;
        if (idx < NN) g_rowptr[idx] += off;
    }
}

__global__ void fill_kernel(const void* __restrict__ ei)
{
    const int is32 = g_is32;
    for (int e = blockIdx.x * blockDim.x + threadIdx.x; e < EE;
         e += gridDim.x * blockDim.x) {
        int row, col;
        load_edge(ei, is32, e, row, col);
        int slot = atomicAdd(&g_cursor[row], 1);
        g_ecol[g_rowptr[row] + slot] = col;
    }
}

// ======================================================================
// mma.sync helpers
// ======================================================================
__device__ __forceinline__ uint32_t smem_u32(const void* p) {
    uint32_t a;
    asm("{ .reg .u64 t; cvta.to.shared.u64 t, %1; cvt.u32.u64 %0, t; }"
        : "=r"(a) : "l"(p));
    return a;
}
__device__ __forceinline__ void ldsm_x4(uint32_t addr, uint32_t& r0, uint32_t& r1,
                                        uint32_t& r2, uint32_t& r3) {
    asm volatile("ldmatrix.sync.aligned.m8n8.x4.shared.b16 {%0,%1,%2,%3}, [%4];"
                 : "=r"(r0), "=r"(r1), "=r"(r2), "=r"(r3) : "r"(addr));
}
__device__ __forceinline__ void ldsm_x2(uint32_t addr, uint32_t& r0, uint32_t& r1) {
    asm volatile("ldmatrix.sync.aligned.m8n8.x2.shared.b16 {%0,%1}, [%2];"
                 : "=r"(r0), "=r"(r1) : "r"(addr));
}
__device__ __forceinline__ void mma16816(float* c, const uint32_t* a,
                                         const uint32_t* b) {
    asm volatile(
        "mma.sync.aligned.m16n8k16.row.col.f32.bf16.bf16.f32 "
        "{%0,%1,%2,%3}, {%4,%5,%6,%7}, {%8,%9}, {%0,%1,%2,%3};"
        : "+f"(c[0]), "+f"(c[1]), "+f"(c[2]), "+f"(c[3])
        : "r"(a[0]), "r"(a[1]), "r"(a[2]), "r"(a[3]), "r"(b[0]), "r"(b[1]));
}

// ======================================================================
// GEMM building blocks (bf16 2-way split, fp32 accumulate)
// Tile: 64 rows x 128 cols, 256 threads (8 warps, 2x4).
// smem ~102 KB -> 2 CTAs/SM for phase overlap.
// ======================================================================
#define TSTRIDE 136
#define A_TILE_ELEMS (64 * TSTRIDE)
#define W_TILE_ELEMS (128 * TSTRIDE)
#define SM_TOTAL ((2 * A_TILE_ELEMS + 2 * W_TILE_ELEMS) * 2)

__device__ __forceinline__ void split_store(__nv_bfloat16* hi, __nv_bfloat16* lo,
                                            int off, float4 v) {
    #pragma unroll
    for (int j = 0; j < 4; j++) {
        float x = (j == 0) ? v.x : (j == 1) ? v.y : (j == 2) ? v.z : v.w;
        __nv_bfloat16 h = __float2bfloat16(x);
        hi[off + j] = h;
        lo[off + j] = __float2bfloat16(x - __bfloat162float(h));
    }
}

// Copy pre-converted W (row-major bf16) into smem tile layout, 16B vectors
__device__ __forceinline__ void copy_w(const __nv_bfloat16* __restrict__ whi,
                                       const __nv_bfloat16* __restrict__ wlo,
                                       __nv_bfloat16* w_hi, __nv_bfloat16* w_lo,
                                       int tid) {
    #pragma unroll
    for (int i = 0; i < 8; i++) {
        int f  = tid + i * 256;      // 8-elem group index 0..2047
        int r  = f >> 4;             // 0..127
        int c8 = f & 15;             // 0..15
        uint4 h = ((const uint4*)whi)[f];
        uint4 l = ((const uint4*)wlo)[f];
        *(uint4*)&w_hi[r * TSTRIDE + c8 * 8] = h;
        *(uint4*)&w_lo[r * TSTRIDE + c8 * 8] = l;
    }
}

// Load + convert 64-row A tile (guarded, optional per-head column scale)
__device__ __forceinline__ void conv_a64(const float* __restrict__ A,
                                         const float* __restrict__ colscale,
                                         __nv_bfloat16* a_hi, __nv_bfloat16* a_lo,
                                         int row0, int tid) {
    #pragma unroll
    for (int i = 0; i < 8; i++) {
        int f  = tid + i * 256;     // float4 index 0..2047
        int r  = f >> 5;            // 0..63
        int c4 = f & 31;
        float4 va = make_float4(0.f, 0.f, 0.f, 0.f);
        int gr = row0 + r;
        if (gr < NN) va = ((const float4*)A)[gr * 32 + c4];
        if (colscale) {
            float sc = __ldg(&colscale[c4 >> 2]);   // head = (c4*4)/16
            va.x *= sc; va.y *= sc; va.z *= sc; va.w *= sc;
        }
        split_store(a_hi, a_lo, r * TSTRIDE + c4 * 4, va);
    }
}

// MMA compute + epilogue, 64x128 tile, warp grid 2(m) x 4(n)
__device__ __forceinline__ void mma_compute_store(
    const __nv_bfloat16* a_hi, const __nv_bfloat16* a_lo,
    const __nv_bfloat16* w_hi, const __nv_bfloat16* w_lo,
    const float* __restrict__ bias, float* __restrict__ out,
    int row0, int wid, int lane)
{
    const int m_warp = (wid >> 2) * 32;   // 0 or 32
    const int n_warp = (wid & 3) * 32;    // 0,32,64,96
    const uint32_t aH_base = smem_u32(a_hi);
    const uint32_t aL_base = smem_u32(a_lo);
    const uint32_t wH_base = smem_u32(w_hi);
    const uint32_t wL_base = smem_u32(w_lo);
    const uint32_t a_lane_off =
        (uint32_t)(((lane & 15)) * TSTRIDE + 8 * (lane >> 4)) * 2;
    const uint32_t b_lane_off =
        (uint32_t)(((lane & 7)) * TSTRIDE + 8 * ((lane >> 3) & 1)) * 2;

    float acc[2][4][4];
    #pragma unroll
    for (int mt = 0; mt < 2; mt++)
        #pragma unroll
        for (int nt = 0; nt < 4; nt++)
            #pragma unroll
            for (int j = 0; j < 4; j++) acc[mt][nt][j] = 0.f;

    #pragma unroll
    for (int kt = 0; kt < 8; kt++) {
        const uint32_t koff = kt * 32;   // 16 bf16 = 32 bytes
        uint32_t aH[2][4], aL[2][4];
        #pragma unroll
        for (int mt = 0; mt < 2; mt++) {
            uint32_t ra = (uint32_t)((m_warp + mt * 16) * TSTRIDE * 2) + a_lane_off + koff;
            ldsm_x4(aH_base + ra, aH[mt][0], aH[mt][1], aH[mt][2], aH[mt][3]);
            ldsm_x4(aL_base + ra, aL[mt][0], aL[mt][1], aL[mt][2], aL[mt][3]);
        }
        #pragma unroll
        for (int nt = 0; nt < 4; nt++) {
            uint32_t rb = (uint32_t)((n_warp + nt * 8) * TSTRIDE * 2) + b_lane_off + koff;
            uint32_t bH[2], bL[2];
            ldsm_x2(wH_base + rb, bH[0], bH[1]);
            ldsm_x2(wL_base + rb, bL[0], bL[1]);
            #pragma unroll
            for (int mt = 0; mt < 2; mt++) {
                mma16816(acc[mt][nt], aH[mt], bH);
                mma16816(acc[mt][nt], aH[mt], bL);
                mma16816(acc[mt][nt], aL[mt], bH);
            }
        }
    }

    const int qrow = lane >> 2;
    const int qcol = (lane & 3) * 2;
    #pragma unroll
    for (int mt = 0; mt < 2; mt++) {
        #pragma unroll
        for (int half = 0; half < 2; half++) {
            int grow = row0 + m_warp + mt * 16 + qrow + half * 8;
            if (grow < NN) {
                #pragma unroll
                for (int nt = 0; nt < 4; nt++) {
                    int col = n_warp + nt * 8 + qcol;
                    float2 o;
                    o.x = acc[mt][nt][half * 2 + 0] + __ldg(&bias[col]);
                    o.y = acc[mt][nt][half * 2 + 1] + __ldg(&bias[col + 1]);
                    *(float2*)&out[grow * 128 + col] = o;
                }
            }
        }
    }
}

// Fused Q/K/V GEMM: load+convert feat tile once, 3 pre-converted weights
__global__ __launch_bounds__(256) void gemm_qkv_kernel(
    const float* __restrict__ A,
    const float* __restrict__ bq, float* __restrict__ oq,
    const float* __restrict__ bk, float* __restrict__ ok,
    const float* __restrict__ bv, float* __restrict__ ov)
{
    extern __shared__ __nv_bfloat16 smem[];
    __nv_bfloat16* a_hi = smem;
    __nv_bfloat16* a_lo = smem + A_TILE_ELEMS;
    __nv_bfloat16* w_hi = smem + 2 * A_TILE_ELEMS;
    __nv_bfloat16* w_lo = smem + 2 * A_TILE_ELEMS + W_TILE_ELEMS;

    const int tid  = threadIdx.x;
    const int wid  = tid >> 5;
    const int lane = tid & 31;
    const int row0 = blockIdx.x * 64;

    conv_a64(A, (const float*)0, a_hi, a_lo, row0, tid);

    const float* bs[3] = {bq, bk, bv};
    float*       os[3] = {oq, ok, ov};
    #pragma unroll 1
    for (int w = 0; w < 3; w++) {
        copy_w(g_whi[w], g_wlo[w], w_hi, w_lo, tid);
        __syncthreads();
        mma_compute_store(a_hi, a_lo, w_hi, w_lo, bs[w], os[w], row0, wid, lane);
        __syncthreads();
    }
}

// Final Wo GEMM: per-head column scale on A, pre-converted W index 3
__global__ __launch_bounds__(256) void gemm_mma_kernel(
    const float* __restrict__ A,
    const float* __restrict__ bias,
    float* __restrict__ out,
    const float* __restrict__ colscale)
{
    extern __shared__ __nv_bfloat16 smem[];
    __nv_bfloat16* a_hi = smem;
    __nv_bfloat16* a_lo = smem + A_TILE_ELEMS;
    __nv_bfloat16* w_hi = smem + 2 * A_TILE_ELEMS;
    __nv_bfloat16* w_lo = smem + 2 * A_TILE_ELEMS + W_TILE_ELEMS;

    const int tid  = threadIdx.x;
    const int wid  = tid >> 5;
    const int lane = tid & 31;
    const int row0 = blockIdx.x * 64;

    conv_a64(A, colscale, a_hi, a_lo, row0, tid);
    copy_w(g_whi[3], g_wlo[3], w_hi, w_lo, tid);
    __syncthreads();
    mma_compute_store(a_hi, a_lo, w_hi, w_lo, bias, out, row0, wid, lane);
}

// ======================================================================
// Gather: one warp per node; 2 edges in flight per iteration.
// ======================================================================
__global__ __launch_bounds__(GATHER_THREADS) void gather_kernel()
{
    const int lane = threadIdx.x & 31;
    const int warp = (blockIdx.x * blockDim.x + threadIdx.x) >> 5;
    const int h = lane >> 2;
    float hsum = 0.f;

    for (int n = warp; n < NN; n += TOTAL_WARPS) {
        float4 q4 = ((const float4*)g_q)[n * 32 + lane];
        float4 a = make_float4(0.f, 0.f, 0.f, 0.f);
        const int beg = g_rowptr[n];
        const int end = g_rowptr[n + 1];
        int j = beg;
        for (; j + 1 < end; j += 2) {
            int c0 = __ldg(&g_ecol[j]);
            int c1 = __ldg(&g_ecol[j + 1]);
            float4 k0 = ((const float4*)g_k)[c0 * 32 + lane];
            float4 v0 = ((const float4*)g_v)[c0 * 32 + lane];
            float4 k1 = ((const float4*)g_k)[c1 * 32 + lane];
            float4 v1 = ((const float4*)g_v)[c1 * 32 + lane];
            float p0 = q4.x * k0.x + q4.y * k0.y + q4.z * k0.z + q4.w * k0.w;
            float p1 = q4.x * k1.x + q4.y * k1.y + q4.z * k1.z + q4.w * k1.w;
            p0 += __shfl_xor_sync(0xFFFFFFFFu, p0, 1);
            p1 += __shfl_xor_sync(0xFFFFFFFFu, p1, 1);
            p0 += __shfl_xor_sync(0xFFFFFFFFu, p0, 2);
            p1 += __shfl_xor_sync(0xFFFFFFFFu, p1, 2);
            float w0 = __expf(p0 * 0.25f);
            float w1 = __expf(p1 * 0.25f);
            if ((lane & 3) == 0) hsum += w0 + w1;
            a.x += w0 * v0.x + w1 * v1.x;
            a.y += w0 * v0.y + w1 * v1.y;
            a.z += w0 * v0.z + w1 * v1.z;
            a.w += w0 * v0.w + w1 * v1.w;
        }
        if (j < end) {
            int c0 = __ldg(&g_ecol[j]);
            float4 k0 = ((const float4*)g_k)[c0 * 32 + lane];
            float4 v0 = ((const float4*)g_v)[c0 * 32 + lane];
            float p0 = q4.x * k0.x + q4.y * k0.y + q4.z * k0.z + q4.w * k0.w;
            p0 += __shfl_xor_sync(0xFFFFFFFFu, p0, 1);
            p0 += __shfl_xor_sync(0xFFFFFFFFu, p0, 2);
            float w0 = __expf(p0 * 0.25f);
            if ((lane & 3) == 0) hsum += w0;
            a.x += w0 * v0.x;
            a.y += w0 * v0.y;
            a.z += w0 * v0.z;
            a.w += w0 * v0.w;
        }
        ((float4*)g_acc)[n * 32 + lane] = a;
    }
    if ((lane & 3) == 0) g_partial[warp * 8 + h] = hsum;
}

// ======================================================================
// Deterministic denominator reduction: 1 block, fixed summation order.
// ======================================================================
__global__ void denom_kernel()
{
    __shared__ float sh[256];
    const int t = threadIdx.x;
    const int h = t & 7;
    const int i0 = t >> 3;
    float s = 0.f;
    for (int i = i0; i < TOTAL_WARPS; i += 32)
        s += g_partial[i * 8 + h];
    sh[t] = s;
    __syncthreads();
    if (t < 8) {
        float tot = 0.f;
        #pragma unroll
        for (int j = 0; j < 32; j++) tot += sh[t + j * 8];
        g_inv_denom[t] = 1.0f / tot;
    }
}

// ======================================================================
// kernel_launch
// ======================================================================
extern "C" void kernel_launch(void* const* d_in, const int* in_sizes, int n_in,
                              void* d_out, int out_size)
{
    const float* feat = (const float*)d_in[0];
    const void*  ei   = d_in[1];
    const float* Wq   = (const float*)d_in[2];
    const float* bq   = (const float*)d_in[3];
    const float* Wk   = (const float*)d_in[4];
    const float* bk   = (const float*)d_in[5];
    const float* Wv   = (const float*)d_in[6];
    const float* bv   = (const float*)d_in[7];
    const float* Wo   = (const float*)d_in[8];
    const float* bo   = (const float*)d_in[9];
    float* out = (float*)d_out;

    cudaFuncSetAttribute(gemm_qkv_kernel,
                         cudaFuncAttributeMaxDynamicSharedMemorySize, SM_TOTAL);
    cudaFuncSetAttribute(gemm_mma_kernel,
                         cudaFuncAttributeMaxDynamicSharedMemorySize, SM_TOTAL);

    float* q;   cudaGetSymbolAddress((void**)&q,   g_q);
    float* k;   cudaGetSymbolAddress((void**)&k,   g_k);
    float* v;   cudaGetSymbolAddress((void**)&v,   g_v);
    float* acc; cudaGetSymbolAddress((void**)&acc, g_acc);
    float* inv; cudaGetSymbolAddress((void**)&inv, g_inv_denom);

    const int gemm_blocks = (NN + 63) / 64;  // 1563

    detect_kernel<<<1, 1>>>((const int*)ei);
    convw_kernel<<<64, 256>>>(Wq, Wk, Wv, Wo);
    zero_hist_kernel<<<391, 256>>>();
    count_kernel<<<1280, 256>>>(ei);
    scan1_kernel<<<SCAN_BLOCKS, 256>>>();
    scan2_kernel<<<1, 128>>>();
    scan3_kernel<<<SCAN_BLOCKS, 256>>>();
    fill_kernel<<<1280, 256>>>(ei);

    gemm_qkv_kernel<<<gemm_blocks, 256, SM_TOTAL>>>(feat, bq, q, bk, k, bv, v);

    gather_kernel<<<GATHER_BLOCKS, GATHER_THREADS>>>();
    denom_kernel<<<1, 256>>>();

    gemm_mma_kernel<<<gemm_blocks, 256, SM_TOTAL>>>(acc, bo, out, inv);
}